// round 7
// baseline (speedup 1.0000x reference)
#include <cuda_runtime.h>

#define B_   4
#define C_   128
#define H_   64
#define W_   64
#define KS_  7
#define PAD_ 3
#define NC_  8      // channel chunks
#define CC_  16     // channels per chunk ( == O/GROUPS, so chunk == group )
#define HW_  (H_*W_)

#define CHUNK_STRIDE_ ((size_t)H_*W_*CC_)            // per (b,cc) plane
#define MAT_STRIDE_   ((size_t)B_*NC_*H_*W_*CC_)     // per q/k/v matrix

// Scratch for q,k,v in chunked pixel-major layout: [mat][b][cc][y][x][16]
__device__ __align__(16) float g_qkv[3ull * B_ * NC_ * H_ * W_ * CC_];

// ---------------- packed f32x2 helpers ----------------
__device__ __forceinline__ unsigned long long pack2(float a, float b) {
    unsigned long long r;
    asm("mov.b64 %0, {%1, %2};" : "=l"(r) : "f"(a), "f"(b));
    return r;
}
__device__ __forceinline__ unsigned long long fma2(unsigned long long a,
                                                   unsigned long long b,
                                                   unsigned long long c) {
    unsigned long long d;
    asm("fma.rn.f32x2 %0, %1, %2, %3;" : "=l"(d) : "l"(a), "l"(b), "l"(c));
    return d;
}

// ---------------- Kernel 1: fused QKV projection (unchanged) -----------------
__global__ __launch_bounds__(256) void proj_kernel(
    const float* __restrict__ x, const float* __restrict__ wq,
    const float* __restrict__ wk, const float* __restrict__ wv)
{
    __shared__ float Xs[16][64];
    __shared__ float Ws[16][132];

    const int row = blockIdx.x;
    const int b = row >> 6, h = row & 63;
    const int mat = blockIdx.y;
    const float* wm = (mat == 0) ? wq : (mat == 1 ? wk : wv);

    const int t = threadIdx.x;
    const int pxg  = t & 15;
    const int outg = t >> 4;

    unsigned long long acc2[4][4];
#pragma unroll
    for (int i = 0; i < 4; i++)
#pragma unroll
        for (int j = 0; j < 4; j++) acc2[i][j] = 0ull;

    const float* xrow = x + ((size_t)b * C_ * H_ + h) * W_;

    for (int c0 = 0; c0 < C_; c0 += 16) {
        __syncthreads();
        for (int i = t; i < 16 * 64; i += 256) {
            int kk = i >> 6, px = i & 63;
            Xs[kk][px] = xrow[(size_t)(c0 + kk) * HW_ + px];
        }
        for (int i = t; i < 16 * 128; i += 256) {
            int o = i >> 4, kk = i & 15;
            Ws[kk][o] = wm[o * C_ + c0 + kk];
        }
        __syncthreads();
#pragma unroll
        for (int kk = 0; kk < 16; kk++) {
            float4 xv = *(const float4*)&Xs[kk][pxg * 4];
            ulonglong2 wA = *(const ulonglong2*)&Ws[kk][outg * 8];
            ulonglong2 wB = *(const ulonglong2*)&Ws[kk][outg * 8 + 4];
            float xs4[4] = {xv.x, xv.y, xv.z, xv.w};
#pragma unroll
            for (int i = 0; i < 4; i++) {
                unsigned long long xb = pack2(xs4[i], xs4[i]);
                acc2[i][0] = fma2(xb, wA.x, acc2[i][0]);
                acc2[i][1] = fma2(xb, wA.y, acc2[i][1]);
                acc2[i][2] = fma2(xb, wB.x, acc2[i][2]);
                acc2[i][3] = fma2(xb, wB.y, acc2[i][3]);
            }
        }
    }

    const int cc = outg >> 1;
    const int cbase = (outg & 1) * 8;
    float* ob = g_qkv + (size_t)mat * MAT_STRIDE_ +
                ((size_t)(b * NC_ + cc) * H_ + h) * W_ * CC_ + cbase;
#pragma unroll
    for (int i = 0; i < 4; i++) {
        int ww = pxg * 4 + i;
        ulonglong2* p = (ulonglong2*)(ob + (size_t)ww * CC_);
        p[0] = make_ulonglong2(acc2[i][0], acc2[i][1]);
        p[1] = make_ulonglong2(acc2[i][2], acc2[i][3]);
    }
}

// ---------------- Kernel 2: windowed attention -------------------------------
// 8x8 tiles, 256 blocks, 8 warps/block, warp == chunk, 2 vertical px/thread.
#define TW_ 8
#define TH_ 8
#define KW_ (TW_ + KS_ - 1)        // 14
#define KH_ (TH_ + KS_ - 1)        // 14
#define NW_ 8                       // warps per block == chunks
#define PLANE_ (KH_ * KW_)          // 196
#define TILE_F4_ (4 * PLANE_)       // 784 float4 per chunk tile
#define RPS_ 65                     // reduction vector stride (65%32==1)
#define RED_BUF_ (64 * RPS_)        // floats per reduction buffer
#define SMEM_TILES_F4_ (NW_ * TILE_F4_)
#define SMEM_BYTES_ (SMEM_TILES_F4_ * 16 + 4 * RED_BUF_ * 4 + 112 * 4)

__device__ __forceinline__ void cp_stage_w(float4* __restrict__ dst,
                                           const float* __restrict__ base,
                                           int y0, int x0, int lane)
{
#pragma unroll
    for (int it = 0; it < 25; it++) {
        int i = lane + it * 32;
        if (i < TILE_F4_) {
            int c4  = i / PLANE_;
            int rem = i - c4 * PLANE_;
            int yy  = rem / KW_;
            int xx  = rem - yy * KW_;
            int gy = y0 - PAD_ + yy, gx = x0 - PAD_ + xx;
            bool inb = ((unsigned)gy < H_) && ((unsigned)gx < W_);
            const float* src = base + ((size_t)(inb ? gy : 0) * W_ + (inb ? gx : 0)) * CC_ + c4 * 4;
            unsigned daddr = (unsigned)__cvta_generic_to_shared(dst + i);
            int sz = inb ? 16 : 0;
            asm volatile("cp.async.cg.shared.global [%0], [%1], 16, %2;"
                         :: "r"(daddr), "l"(src), "r"(sz));
        }
    }
}
__device__ __forceinline__ void cp_commit() {
    asm volatile("cp.async.commit_group;" ::: "memory");
}
__device__ __forceinline__ void cp_wait_all() {
    asm volatile("cp.async.wait_all;" ::: "memory");
}

__device__ __forceinline__ float dot4(float4 a, float4 b, float s) {
    s = fmaf(a.x, b.x, s); s = fmaf(a.y, b.y, s);
    s = fmaf(a.z, b.z, s); s = fmaf(a.w, b.w, s);
    return s;
}
__device__ __forceinline__ void axpy4(float a, float4 v, float4& o) {
    o.x = fmaf(a, v.x, o.x); o.y = fmaf(a, v.y, o.y);
    o.z = fmaf(a, v.z, o.z); o.w = fmaf(a, v.w, o.w);
}

__global__ void __launch_bounds__(256, 1) attn_kernel(
    const float* __restrict__ relx, const float* __restrict__ rely,
    float* __restrict__ out)
{
    extern __shared__ float4 sm4[];
    float* red  = (float*)(sm4 + SMEM_TILES_F4_);
    float* srel = red + 4 * RED_BUF_;

    const int t    = threadIdx.x;
    const int w    = t >> 5;           // warp id == chunk id
    const int lane = t & 31;
    const int tx   = lane & 7;
    const int tyh  = lane >> 3;        // 0..3; rows 2*tyh, 2*tyh+1
    const int b    = blockIdx.z;
    const int x0   = blockIdx.x * TW_, y0 = blockIdx.y * TH_;
    const int px   = x0 + tx;
    const int py0  = y0 + 2 * tyh, py1 = py0 + 1;

    if (t < 112) srel[t] = (t < 56) ? relx[t] : rely[t - 56];

    float4* tile = sm4 + w * TILE_F4_;
    const float* kb = g_qkv + MAT_STRIDE_;
    const float* vb = g_qkv + 2 * MAT_STRIDE_;
    const size_t choff = (size_t)(b * NC_ + w) * CHUNK_STRIDE_;

    // stage this warp's K chunk tile
    cp_stage_w(tile, kb + choff, y0, x0, lane);
    cp_commit();
    cp_wait_all();
    __syncwarp();

    // q for both pixels of this thread, this chunk
    float q0f[16], q1f[16];
    {
        const float4* qp0 = (const float4*)(g_qkv + choff + ((size_t)py0 * W_ + px) * CC_);
        const float4* qp1 = (const float4*)(g_qkv + choff + ((size_t)py1 * W_ + px) * CC_);
#pragma unroll
        for (int i = 0; i < 4; i++) {
            float4 a = qp0[i]; float4 c = qp1[i];
            q0f[4*i] = a.x; q0f[4*i+1] = a.y; q0f[4*i+2] = a.z; q0f[4*i+3] = a.w;
            q1f[4*i] = c.x; q1f[4*i+1] = c.y; q1f[4*i+2] = c.z; q1f[4*i+3] = c.w;
        }
    }
    float4 qa0 = *(float4*)&q0f[0],  qa1 = *(float4*)&q0f[4],
           qa2 = *(float4*)&q0f[8],  qa3 = *(float4*)&q0f[12];
    float4 qb0 = *(float4*)&q1f[0],  qb1 = *(float4*)&q1f[4],
           qb2 = *(float4*)&q1f[8],  qb3 = *(float4*)&q1f[12];

    float l0[49], l1[49];
#pragma unroll
    for (int i = 0; i < 49; i++) { l0[i] = 0.f; l1[i] = 0.f; }

    // ---- pass 1: partial logits for this chunk; rows reused across the 2 px
#pragma unroll
    for (int r = 0; r < 8; r++) {
#pragma unroll
        for (int kj = 0; kj < 7; kj++) {
            int o = (2 * tyh + r) * KW_ + tx + kj;
            float4 k0 = tile[0 * PLANE_ + o];
            float4 k1 = tile[1 * PLANE_ + o];
            float4 k2 = tile[2 * PLANE_ + o];
            float4 k3 = tile[3 * PLANE_ + o];
            if (r < 7) {
                float s = l0[r * 7 + kj];
                s = dot4(qa0, k0, s); s = dot4(qa1, k1, s);
                s = dot4(qa2, k2, s); s = dot4(qa3, k3, s);
                l0[r * 7 + kj] = s;
            }
            if (r > 0) {
                float s = l1[(r - 1) * 7 + kj];
                s = dot4(qb0, k0, s); s = dot4(qb1, k1, s);
                s = dot4(qb2, k2, s); s = dot4(qb3, k3, s);
                l1[(r - 1) * 7 + kj] = s;
            }
        }
    }

    // warp done with its K tile -> start its V copy; completes under reduction
    __syncwarp();
    cp_stage_w(tile, vb + choff, y0, x0, lane);
    cp_commit();

    // ---- tree reduction across 8 warps (values: 49 logits + 16 q) ----
    // reduction pixel index: rpx0 = lane (rows 2*tyh), rpx1 = lane+32 (odd rows)
    const int rpx0 = lane, rpx1 = lane + 32;
    float* r0 = red;
    float* r1 = red + RED_BUF_;
    float* r2 = red + 2 * RED_BUF_;
    float* r3 = red + 3 * RED_BUF_;

#define STORE_VEC(BASE, RPX, L, QF) do {                          \
        float* _p = (BASE) + (RPX) * RPS_;                        \
        _Pragma("unroll") for (int j = 0; j < 49; j++) _p[j] = (L)[j]; \
        _Pragma("unroll") for (int j = 0; j < 16; j++) _p[49 + j] = (QF)[j]; \
    } while (0)
#define ADD_VEC(BASE, RPX, L, QF) do {                            \
        const float* _p = (BASE) + (RPX) * RPS_;                  \
        _Pragma("unroll") for (int j = 0; j < 49; j++) (L)[j] += _p[j]; \
        _Pragma("unroll") for (int j = 0; j < 16; j++) (QF)[j] += _p[49 + j]; \
    } while (0)

    __syncthreads();
    if (w >= 4) {
        float* base = (w == 4) ? r0 : (w == 5) ? r1 : (w == 6) ? r2 : r3;
        STORE_VEC(base, rpx0, l0, q0f);
        STORE_VEC(base, rpx1, l1, q1f);
    }
    __syncthreads();
    if (w < 4) {
        float* base = (w == 0) ? r0 : (w == 1) ? r1 : (w == 2) ? r2 : r3;
        ADD_VEC(base, rpx0, l0, q0f);
        ADD_VEC(base, rpx1, l1, q1f);
    }
    __syncthreads();
    if (w == 2 || w == 3) {
        float* base = (w == 2) ? r0 : r1;
        STORE_VEC(base, rpx0, l0, q0f);
        STORE_VEC(base, rpx1, l1, q1f);
    }
    __syncthreads();
    if (w < 2) {
        float* base = (w == 0) ? r0 : r1;
        ADD_VEC(base, rpx0, l0, q0f);
        ADD_VEC(base, rpx1, l1, q1f);
    }
    __syncthreads();
    if (w < 2) {
        float* base = (w == 0) ? r0 : r1;
        STORE_VEC(base, rpx0, l0, q0f);
        STORE_VEC(base, rpx1, l1, q1f);
    }
    __syncthreads();
    // final: every thread reads full sums for its 2 pixels
    {
        const float* pa0 = r0 + rpx0 * RPS_;
        const float* pb0 = r1 + rpx0 * RPS_;
        const float* pa1 = r0 + rpx1 * RPS_;
        const float* pb1 = r1 + rpx1 * RPS_;
#pragma unroll
        for (int j = 0; j < 49; j++) { l0[j] = pa0[j] + pb0[j]; l1[j] = pa1[j] + pb1[j]; }
#pragma unroll
        for (int j = 0; j < 16; j++) { q0f[j] = pa0[49 + j] + pb0[49 + j];
                                       q1f[j] = pa1[49 + j] + pb1[49 + j]; }
    }

    // ---- bias + softmax per pixel (redundant across warps) ----
#pragma unroll
    for (int p = 0; p < 2; p++) {
        float* l  = p ? l1 : l0;
        float* qf = p ? q1f : q0f;
        float bx[7], by[7];
#pragma unroll
        for (int kj = 0; kj < 7; kj++) {
            float s = 0.f;
#pragma unroll
            for (int xi = 0; xi < 8; xi++) s = fmaf(qf[xi], srel[xi * 7 + kj], s);
            bx[kj] = s;
        }
#pragma unroll
        for (int ki = 0; ki < 7; ki++) {
            float s = 0.f;
#pragma unroll
            for (int yi = 0; yi < 8; yi++) s = fmaf(qf[8 + yi], srel[56 + yi * 7 + ki], s);
            by[ki] = s;
        }
        float m = -1e30f;
#pragma unroll
        for (int ki = 0; ki < 7; ki++)
#pragma unroll
            for (int kj = 0; kj < 7; kj++) {
                float v = l[ki * 7 + kj] + bx[kj] + by[ki];
                l[ki * 7 + kj] = v;
                m = fmaxf(m, v);
            }
        float ssum = 0.f;
#pragma unroll
        for (int i = 0; i < 49; i++) { float e = __expf(l[i] - m); l[i] = e; ssum += e; }
        float inv = 1.f / ssum;
#pragma unroll
        for (int i = 0; i < 49; i++) l[i] *= inv;
    }

    // ---- pass 2: out for this warp's chunk (V already staged) ----
    cp_wait_all();
    __syncwarp();

    float4 oa0 = make_float4(0.f,0.f,0.f,0.f), oa1 = oa0, oa2 = oa0, oa3 = oa0;
    float4 ob0 = oa0, ob1 = oa0, ob2 = oa0, ob3 = oa0;
#pragma unroll
    for (int r = 0; r < 8; r++) {
#pragma unroll
        for (int kj = 0; kj < 7; kj++) {
            int o = (2 * tyh + r) * KW_ + tx + kj;
            float4 v0 = tile[0 * PLANE_ + o];
            float4 v1 = tile[1 * PLANE_ + o];
            float4 v2 = tile[2 * PLANE_ + o];
            float4 v3 = tile[3 * PLANE_ + o];
            if (r < 7) {
                float a = l0[r * 7 + kj];
                axpy4(a, v0, oa0); axpy4(a, v1, oa1);
                axpy4(a, v2, oa2); axpy4(a, v3, oa3);
            }
            if (r > 0) {
                float a = l1[(r - 1) * 7 + kj];
                axpy4(a, v0, ob0); axpy4(a, v1, ob1);
                axpy4(a, v2, ob2); axpy4(a, v3, ob3);
            }
        }
    }

    // write BCHW: channels w*16 .. w*16+15
    {
        size_t o0 = ((size_t)(b * C_ + w * CC_) * H_ + py0) * W_ + px;
        size_t o1 = ((size_t)(b * C_ + w * CC_) * H_ + py1) * W_ + px;
        float oav[16] = {oa0.x,oa0.y,oa0.z,oa0.w, oa1.x,oa1.y,oa1.z,oa1.w,
                         oa2.x,oa2.y,oa2.z,oa2.w, oa3.x,oa3.y,oa3.z,oa3.w};
        float obv[16] = {ob0.x,ob0.y,ob0.z,ob0.w, ob1.x,ob1.y,ob1.z,ob1.w,
                         ob2.x,ob2.y,ob2.z,ob2.w, ob3.x,ob3.y,ob3.z,ob3.w};
#pragma unroll
        for (int c = 0; c < 16; c++) {
            out[o0 + (size_t)c * HW_] = oav[c];
            out[o1 + (size_t)c * HW_] = obv[c];
        }
    }
}

// ---------------- launch -----------------------------------------------------
extern "C" void kernel_launch(void* const* d_in, const int* in_sizes, int n_in,
                              void* d_out, int out_size)
{
    const float* x    = (const float*)d_in[0];
    const float* wq   = (const float*)d_in[1];
    const float* wk   = (const float*)d_in[2];
    const float* wv   = (const float*)d_in[3];
    const float* relx = (const float*)d_in[4];
    const float* rely = (const float*)d_in[5];
    float* out = (float*)d_out;

    cudaFuncSetAttribute(attn_kernel,
                         cudaFuncAttributeMaxDynamicSharedMemorySize, SMEM_BYTES_);

    proj_kernel<<<dim3(B_ * H_, 3), 256>>>(x, wq, wk, wv);
    attn_kernel<<<dim3(W_ / TW_, H_ / TH_, B_), 256, SMEM_BYTES_>>>(relx, rely, out);
}

// round 9
// speedup vs baseline: 1.1871x; 1.1871x over previous
#include <cuda_runtime.h>
#include <cuda_bf16.h>
#include <cstdint>

#define B_   4
#define C_   128
#define H_   64
#define W_   64
#define KS_  7
#define PAD_ 3
#define NC_  8      // channel chunks
#define CC_  16     // channels per chunk ( == O/GROUPS )
#define HW_  (H_*W_)

#define CHUNK_STRIDE_ ((size_t)H_*W_*CC_)            // per (b,cc) plane
#define MAT_STRIDE_   ((size_t)B_*NC_*H_*W_*CC_)     // per q/k/v matrix

// Scratch for q,k,v in chunked pixel-major layout: [mat][b][cc][y][x][16]
__device__ __align__(16) float g_qkv[3ull * B_ * NC_ * H_ * W_ * CC_];

// Pre-split bf16 W images, padded [n][136] halfs (272B rows): [mat][hi/lo]
#define WLDH_ 136
__device__ __align__(16) unsigned short g_w16[3][2][128 * WLDH_];

// ---------------- Kernel 0: W -> split-bf16 padded images --------------------
__global__ __launch_bounds__(256) void wprep_kernel(
    const float* __restrict__ wq, const float* __restrict__ wk,
    const float* __restrict__ wv)
{
    const int m = blockIdx.x;
    const float* w = (m == 0) ? wq : (m == 1) ? wk : wv;
    const int t = threadIdx.x;
    for (int i = t; i < 128 * 128; i += 256) {
        int n = i >> 7, k = i & 127;
        float a = w[n * 128 + k];
        __nv_bfloat16 hi = __float2bfloat16(a);
        __nv_bfloat16 lo = __float2bfloat16(a - __bfloat162float(hi));
        g_w16[m][0][n * WLDH_ + k] = __bfloat16_as_ushort(hi);
        g_w16[m][1][n * WLDH_ + k] = __bfloat16_as_ushort(lo);
    }
}

// ---------------- Kernel 1: QKV projection via mma.sync bf16-split -----------
// grid = (32 px-tiles, 4 batches, 3 mats); 256 threads.
// SMEM: A hi/lo stored [ch=128][px=136 pitch] halfs; W hi/lo [n=128][k=136 pitch].
#define ALD_ 136                       // pitch in halfs (272 B rows)
#define SA_HI_ 0
#define SA_LO_ (SA_HI_ + 128 * ALD_ * 2)          // 34816
#define SW_HI_ (SA_LO_ + 128 * ALD_ * 2)          // 69632
#define SW_LO_ (SW_HI_ + 128 * WLDH_ * 2)         // 104448
#define PSM_BYTES_ (SW_LO_ + 128 * WLDH_ * 2)     // 139264

__device__ __forceinline__ uint32_t smem_u32(const void* p) {
    uint32_t a;
    asm("{ .reg .u64 t; cvta.to.shared.u64 t, %1; cvt.u32.u64 %0, t; }"
        : "=r"(a) : "l"(p));
    return a;
}
__device__ __forceinline__ void ldsm_x4_trans(uint32_t* r, uint32_t addr) {
    asm volatile("ldmatrix.sync.aligned.m8n8.x4.trans.shared.b16 {%0,%1,%2,%3}, [%4];"
                 : "=r"(r[0]), "=r"(r[1]), "=r"(r[2]), "=r"(r[3]) : "r"(addr));
}
__device__ __forceinline__ void ldsm_x2(uint32_t& b0, uint32_t& b1, uint32_t addr) {
    asm volatile("ldmatrix.sync.aligned.m8n8.x2.shared.b16 {%0,%1}, [%2];"
                 : "=r"(b0), "=r"(b1) : "r"(addr));
}
__device__ __forceinline__ void mma16816(float* d, const uint32_t* a,
                                         uint32_t b0, uint32_t b1) {
    asm volatile(
        "mma.sync.aligned.m16n8k16.row.col.f32.bf16.bf16.f32 "
        "{%0,%1,%2,%3}, {%4,%5,%6,%7}, {%8,%9}, {%0,%1,%2,%3};"
        : "+f"(d[0]), "+f"(d[1]), "+f"(d[2]), "+f"(d[3])
        : "r"(a[0]), "r"(a[1]), "r"(a[2]), "r"(a[3]), "r"(b0), "r"(b1));
}

__global__ void __launch_bounds__(256, 1) proj_mma_kernel(const float* __restrict__ x)
{
    extern __shared__ char sm[];
    const uint32_t smb = smem_u32(sm);
    const int t = threadIdx.x;
    const int pxbase = blockIdx.x * 128;
    const int b = blockIdx.y;
    const int mat = blockIdx.z;

    // ---- X tile: load [128ch][128px], split bf16, store [ch][px] (8B STS) ----
    for (int j = 0; j < 16; j++) {
        int idx = t + j * 256;            // 4096 float4 loads
        int c  = idx >> 5;                // 32 float4 per channel row
        int p4 = idx & 31;
        float4 v = *(const float4*)(x + ((size_t)(b * C_ + c)) * HW_ + pxbase + p4 * 4);
        float vv[4] = {v.x, v.y, v.z, v.w};
        unsigned short h[4], l[4];
#pragma unroll
        for (int e = 0; e < 4; e++) {
            __nv_bfloat16 hb = __float2bfloat16(vv[e]);
            __nv_bfloat16 lb = __float2bfloat16(vv[e] - __bfloat162float(hb));
            h[e] = __bfloat16_as_ushort(hb);
            l[e] = __bfloat16_as_ushort(lb);
        }
        uint32_t off = (uint32_t)(c * ALD_ + p4 * 4) * 2;
        *(uint2*)(sm + SA_HI_ + off) = make_uint2(
            (uint32_t)h[0] | ((uint32_t)h[1] << 16),
            (uint32_t)h[2] | ((uint32_t)h[3] << 16));
        *(uint2*)(sm + SA_LO_ + off) = make_uint2(
            (uint32_t)l[0] | ((uint32_t)l[1] << 16),
            (uint32_t)l[2] | ((uint32_t)l[3] << 16));
    }
    // ---- copy W hi+lo images (byte-exact, contiguous) ----
    {
        const float4* src = (const float4*)g_w16[mat][0];
        float4* dst = (float4*)(sm + SW_HI_);
        for (int i = t; i < (2 * 128 * WLDH_ * 2) / 16; i += 256) dst[i] = src[i];
    }
    __syncthreads();

    // ---- warp tiles: warp w -> px strip (w&3)*32, out half (w>>2)*64 ----
    const int w = t >> 5, lane = t & 31;
    const int m0 = (w & 3) * 32;
    const int n0 = (w >> 2) * 64;
    const int lq = lane & 15;

    // A (trans) lane address base: row k = (lane&7) + ((lane>>4)&1)*8, col m
    const uint32_t a_base = smb + SA_HI_ +
        (uint32_t)(((lane & 7) + ((lane >> 4) & 1) * 8) * ALD_ +
                   (m0 + ((lane >> 3) & 1) * 8)) * 2;
    // B lane address base: row n = n0 + (lq&7), k byte offset ((lq>>3)&1)*16
    const uint32_t b_base = smb + SW_HI_ +
        (uint32_t)((n0 + (lq & 7)) * WLDH_) * 2 + ((lq >> 3) & 1) * 16;

    float acc[2][8][4];
#pragma unroll
    for (int mt = 0; mt < 2; mt++)
#pragma unroll
        for (int nt = 0; nt < 8; nt++)
#pragma unroll
            for (int e = 0; e < 4; e++) acc[mt][nt][e] = 0.f;

#pragma unroll
    for (int ks = 0; ks < 8; ks++) {
        uint32_t ahi[2][4], alo[2][4];
#pragma unroll
        for (int mt = 0; mt < 2; mt++) {
            uint32_t aa = a_base + (uint32_t)(ks * 16 * ALD_ * 2 + mt * 32);
            ldsm_x4_trans(ahi[mt], aa);
            ldsm_x4_trans(alo[mt], aa + (SA_LO_ - SA_HI_));
        }
#pragma unroll
        for (int nt = 0; nt < 8; nt++) {
            uint32_t ba = b_base + (uint32_t)(nt * 8 * WLDH_ * 2 + ks * 32);
            uint32_t bh0, bh1, bl0, bl1;
            ldsm_x2(bh0, bh1, ba);
            ldsm_x2(bl0, bl1, ba + (SW_LO_ - SW_HI_));
#pragma unroll
            for (int mt = 0; mt < 2; mt++) {
                mma16816(acc[mt][nt], ahi[mt], bh0, bh1);
                mma16816(acc[mt][nt], ahi[mt], bl0, bl1);
                mma16816(acc[mt][nt], alo[mt], bh0, bh1);
            }
        }
    }

    // ---- epilogue: write chunked g_qkv layout ----
#pragma unroll
    for (int mt = 0; mt < 2; mt++) {
#pragma unroll
        for (int nt = 0; nt < 8; nt++) {
            int nn = n0 + nt * 8 + (lane & 3) * 2;   // out channel (even)
            int cc = nn >> 4, ch16 = nn & 15;
            int flat = pxbase + m0 + mt * 16 + (lane >> 2);
            float* dst = g_qkv + (size_t)mat * MAT_STRIDE_ +
                         (size_t)(b * NC_ + cc) * CHUNK_STRIDE_ +
                         (size_t)flat * 16 + ch16;
            *(float2*)dst          = make_float2(acc[mt][nt][0], acc[mt][nt][1]);
            *(float2*)(dst + 128)  = make_float2(acc[mt][nt][2], acc[mt][nt][3]);  // px+8
        }
    }
}

// ---------------- Kernel 2: windowed attention (R5 design: 16x8, 512 thr) ----
#define TW_ 16
#define TH_ 8
#define KW_ (TW_ + KS_ - 1)        // 22
#define KH_ (TH_ + KS_ - 1)        // 14
#define NGR_ 4
#define PLANE_ (KH_ * KW_)          // 308
#define TILE_F4_ (4 * PLANE_)       // 1232
#define RED_STRIDE_ 65
#define SMEM_TILES_F4_ (NGR_ * 2 * TILE_F4_)
#define SMEM_BYTES_ (SMEM_TILES_F4_ * 16 + 128 * RED_STRIDE_ * 4 + 112 * 4)

__device__ __forceinline__ void cp_stage(float4* __restrict__ dst,
                                         const float* __restrict__ base,
                                         int y0, int x0, int pid)
{
#pragma unroll
    for (int it = 0; it < 10; it++) {
        int i = pid + it * 128;
        if (i < TILE_F4_) {
            int c4  = i / PLANE_;
            int rem = i - c4 * PLANE_;
            int yy  = rem / KW_;
            int xx  = rem - yy * KW_;
            int gy = y0 - PAD_ + yy, gx = x0 - PAD_ + xx;
            bool inb = ((unsigned)gy < H_) && ((unsigned)gx < W_);
            const float* src = base + ((size_t)(inb ? gy : 0) * W_ + (inb ? gx : 0)) * CC_ + c4 * 4;
            unsigned daddr = (unsigned)__cvta_generic_to_shared(dst + i);
            int sz = inb ? 16 : 0;
            asm volatile("cp.async.cg.shared.global [%0], [%1], 16, %2;"
                         :: "r"(daddr), "l"(src), "r"(sz));
        }
    }
}
__device__ __forceinline__ void cp_commit() {
    asm volatile("cp.async.commit_group;" ::: "memory");
}
__device__ __forceinline__ void cp_wait_all() {
    asm volatile("cp.async.wait_all;" ::: "memory");
}
__device__ __forceinline__ void group_bar(int g) {
    asm volatile("bar.sync %0, %1;" :: "r"(1 + g), "r"(128) : "memory");
}

__global__ void __launch_bounds__(512, 1) attn_kernel(
    const float* __restrict__ relx, const float* __restrict__ rely,
    float* __restrict__ out)
{
    extern __shared__ float4 sm4[];
    float* red  = (float*)(sm4 + SMEM_TILES_F4_);
    float* srel = red + 128 * RED_STRIDE_;

    const int t   = threadIdx.x;
    const int g   = t >> 7;
    const int pid = t & 127;
    const int tx  = pid & 15, ty = pid >> 4;
    const int b   = blockIdx.z;
    const int x0  = blockIdx.x * TW_, y0 = blockIdx.y * TH_;
    const int px  = x0 + tx, py = y0 + ty;

    if (t < 112) srel[t] = (t < 56) ? relx[t] : rely[t - 56];

    float4* tile = sm4 + g * (2 * TILE_F4_);
    const float* kb = g_qkv + MAT_STRIDE_;
    const float* vb = g_qkv + 2 * MAT_STRIDE_;

    cp_stage(tile,            kb + (size_t)(b * NC_ + 2 * g    ) * CHUNK_STRIDE_, y0, x0, pid);
    cp_stage(tile + TILE_F4_, kb + (size_t)(b * NC_ + 2 * g + 1) * CHUNK_STRIDE_, y0, x0, pid);
    cp_commit();
    cp_wait_all();
    group_bar(g);

    float logit[49];
#pragma unroll
    for (int i = 0; i < 49; i++) logit[i] = 0.f;
    float qxs[8], qys[8];
#pragma unroll
    for (int i = 0; i < 8; i++) { qxs[i] = 0.f; qys[i] = 0.f; }

#pragma unroll 1
    for (int s = 0; s < 2; s++) {
        const float4* tp = tile + s * TILE_F4_;
        const float4* qp = (const float4*)(g_qkv +
            (size_t)(b * NC_ + 2 * g + s) * CHUNK_STRIDE_ +
            ((size_t)py * W_ + px) * CC_);
        float4 q0 = qp[0], q1 = qp[1], q2 = qp[2], q3 = qp[3];

        qxs[0] += q0.x; qxs[1] += q0.y; qxs[2] += q0.z; qxs[3] += q0.w;
        qxs[4] += q1.x; qxs[5] += q1.y; qxs[6] += q1.z; qxs[7] += q1.w;
        qys[0] += q2.x; qys[1] += q2.y; qys[2] += q2.z; qys[3] += q2.w;
        qys[4] += q3.x; qys[5] += q3.y; qys[6] += q3.z; qys[7] += q3.w;

#pragma unroll
        for (int ki = 0; ki < KS_; ki++) {
#pragma unroll
            for (int kj = 0; kj < KS_; kj++) {
                int o = (ty + ki) * KW_ + tx + kj;
                float4 k0 = tp[0 * PLANE_ + o];
                float4 k1 = tp[1 * PLANE_ + o];
                float4 k2 = tp[2 * PLANE_ + o];
                float4 k3 = tp[3 * PLANE_ + o];
                float sacc = logit[ki * KS_ + kj];
                sacc = fmaf(q0.x, k0.x, sacc); sacc = fmaf(q0.y, k0.y, sacc);
                sacc = fmaf(q0.z, k0.z, sacc); sacc = fmaf(q0.w, k0.w, sacc);
                sacc = fmaf(q1.x, k1.x, sacc); sacc = fmaf(q1.y, k1.y, sacc);
                sacc = fmaf(q1.z, k1.z, sacc); sacc = fmaf(q1.w, k1.w, sacc);
                sacc = fmaf(q2.x, k2.x, sacc); sacc = fmaf(q2.y, k2.y, sacc);
                sacc = fmaf(q2.z, k2.z, sacc); sacc = fmaf(q2.w, k2.w, sacc);
                sacc = fmaf(q3.x, k3.x, sacc); sacc = fmaf(q3.y, k3.y, sacc);
                sacc = fmaf(q3.z, k3.z, sacc); sacc = fmaf(q3.w, k3.w, sacc);
                logit[ki * KS_ + kj] = sacc;
            }
        }
    }

    group_bar(g);
    cp_stage(tile,            vb + (size_t)(b * NC_ + 2 * g    ) * CHUNK_STRIDE_, y0, x0, pid);
    cp_stage(tile + TILE_F4_, vb + (size_t)(b * NC_ + 2 * g + 1) * CHUNK_STRIDE_, y0, x0, pid);
    cp_commit();

    float* rp = red + pid * RED_STRIDE_;
    __syncthreads();
    if (g == 0) {
#pragma unroll
        for (int j = 0; j < 49; j++) rp[j] = logit[j];
#pragma unroll
        for (int j = 0; j < 8; j++) { rp[49 + j] = qxs[j]; rp[57 + j] = qys[j]; }
    }
    __syncthreads();
    if (g == 1) {
#pragma unroll
        for (int j = 0; j < 49; j++) rp[j] += logit[j];
#pragma unroll
        for (int j = 0; j < 8; j++) { rp[49 + j] += qxs[j]; rp[57 + j] += qys[j]; }
    }
    __syncthreads();
    if (g == 2) {
#pragma unroll
        for (int j = 0; j < 49; j++) rp[j] += logit[j];
#pragma unroll
        for (int j = 0; j < 8; j++) { rp[49 + j] += qxs[j]; rp[57 + j] += qys[j]; }
    }
    __syncthreads();
    if (g == 3) {
#pragma unroll
        for (int j = 0; j < 49; j++) rp[j] += logit[j];
#pragma unroll
        for (int j = 0; j < 8; j++) { rp[49 + j] += qxs[j]; rp[57 + j] += qys[j]; }
    }
    __syncthreads();
#pragma unroll
    for (int j = 0; j < 49; j++) logit[j] = rp[j];
#pragma unroll
    for (int j = 0; j < 8; j++) { qxs[j] = rp[49 + j]; qys[j] = rp[57 + j]; }

    float bxv[7], byv[7];
#pragma unroll
    for (int kj = 0; kj < 7; kj++) {
        float s = 0.f;
#pragma unroll
        for (int xi = 0; xi < 8; xi++) s = fmaf(qxs[xi], srel[xi * 7 + kj], s);
        bxv[kj] = s;
    }
#pragma unroll
    for (int ki = 0; ki < 7; ki++) {
        float s = 0.f;
#pragma unroll
        for (int yi = 0; yi < 8; yi++) s = fmaf(qys[yi], srel[56 + yi * 7 + ki], s);
        byv[ki] = s;
    }
    float m = -1e30f;
#pragma unroll
    for (int ki = 0; ki < 7; ki++)
#pragma unroll
        for (int kj = 0; kj < 7; kj++) {
            float l = logit[ki * 7 + kj] + bxv[kj] + byv[ki];
            logit[ki * 7 + kj] = l;
            m = fmaxf(m, l);
        }
    float ssum = 0.f;
#pragma unroll
    for (int i = 0; i < 49; i++) {
        float e = __expf(logit[i] - m);
        logit[i] = e;
        ssum += e;
    }
    float inv = 1.f / ssum;
#pragma unroll
    for (int i = 0; i < 49; i++) logit[i] *= inv;

    cp_wait_all();
    group_bar(g);

#pragma unroll 1
    for (int s = 0; s < 2; s++) {
        const float4* tp = tile + s * TILE_F4_;
        float4 o0 = make_float4(0.f, 0.f, 0.f, 0.f), o1 = o0, o2 = o0, o3 = o0;
#pragma unroll
        for (int ki = 0; ki < KS_; ki++) {
#pragma unroll
            for (int kj = 0; kj < KS_; kj++) {
                float a = logit[ki * KS_ + kj];
                int o = (ty + ki) * KW_ + tx + kj;
                float4 v0 = tp[0 * PLANE_ + o];
                float4 v1 = tp[1 * PLANE_ + o];
                float4 v2 = tp[2 * PLANE_ + o];
                float4 v3 = tp[3 * PLANE_ + o];
                o0.x = fmaf(a, v0.x, o0.x); o0.y = fmaf(a, v0.y, o0.y);
                o0.z = fmaf(a, v0.z, o0.z); o0.w = fmaf(a, v0.w, o0.w);
                o1.x = fmaf(a, v1.x, o1.x); o1.y = fmaf(a, v1.y, o1.y);
                o1.z = fmaf(a, v1.z, o1.z); o1.w = fmaf(a, v1.w, o1.w);
                o2.x = fmaf(a, v2.x, o2.x); o2.y = fmaf(a, v2.y, o2.y);
                o2.z = fmaf(a, v2.z, o2.z); o2.w = fmaf(a, v2.w, o2.w);
                o3.x = fmaf(a, v3.x, o3.x); o3.y = fmaf(a, v3.y, o3.y);
                o3.z = fmaf(a, v3.z, o3.z); o3.w = fmaf(a, v3.w, o3.w);
            }
        }
        int c = 2 * g + s;
        size_t ob = ((size_t)(b * C_ + c * CC_) * H_ + py) * W_ + px;
        out[ob +  0 * HW_] = o0.x; out[ob +  1 * HW_] = o0.y;
        out[ob +  2 * HW_] = o0.z; out[ob +  3 * HW_] = o0.w;
        out[ob +  4 * HW_] = o1.x; out[ob +  5 * HW_] = o1.y;
        out[ob +  6 * HW_] = o1.z; out[ob +  7 * HW_] = o1.w;
        out[ob +  8 * HW_] = o2.x; out[ob +  9 * HW_] = o2.y;
        out[ob + 10 * HW_] = o2.z; out[ob + 11 * HW_] = o2.w;
        out[ob + 12 * HW_] = o3.x; out[ob + 13 * HW_] = o3.y;
        out[ob + 14 * HW_] = o3.z; out[ob + 15 * HW_] = o3.w;
    }
}

// ---------------- launch -----------------------------------------------------
extern "C" void kernel_launch(void* const* d_in, const int* in_sizes, int n_in,
                              void* d_out, int out_size)
{
    const float* x    = (const float*)d_in[0];
    const float* wq   = (const float*)d_in[1];
    const float* wk   = (const float*)d_in[2];
    const float* wv   = (const float*)d_in[3];
    const float* relx = (const float*)d_in[4];
    const float* rely = (const float*)d_in[5];
    float* out = (float*)d_out;

    cudaFuncSetAttribute(proj_mma_kernel,
                         cudaFuncAttributeMaxDynamicSharedMemorySize, PSM_BYTES_);
    cudaFuncSetAttribute(attn_kernel,
                         cudaFuncAttributeMaxDynamicSharedMemorySize, SMEM_BYTES_);

    wprep_kernel<<<3, 256>>>(wq, wk, wv);
    proj_mma_kernel<<<dim3(32, B_, 3), 256, PSM_BYTES_>>>(x);
    attn_kernel<<<dim3(W_ / TW_, H_ / TH_, B_), 512, SMEM_BYTES_>>>(relx, rely, out);
}

// round 10
// speedup vs baseline: 1.4509x; 1.2223x over previous
#include <cuda_runtime.h>
#include <cuda_bf16.h>
#include <cstdint>

#define B_   4
#define C_   128
#define H_   64
#define W_   64
#define KS_  7
#define PAD_ 3
#define NC_  8      // channel chunks
#define CC_  16     // channels per chunk ( == O/GROUPS )
#define HW_  (H_*W_)

#define CHUNK_STRIDE_ ((size_t)H_*W_*CC_)            // per (b,cc) plane
#define MAT_STRIDE_   ((size_t)B_*NC_*H_*W_*CC_)     // per q/k/v matrix

// Scratch for q,k,v in chunked pixel-major layout: [mat][b][cc][y][x][16]
__device__ __align__(16) float g_qkv[3ull * B_ * NC_ * H_ * W_ * CC_];

// ---------------- Kernel 1: QKV projection via mma.sync bf16-split -----------
// grid = (32 px-tiles, 4 batches, 3 mats); 256 threads.
// SMEM: A hi/lo stored [ch=128][px=136 pitch] halfs; W hi/lo [n=128][k=136 pitch].
#define WLDH_ 136
#define ALD_ 136                       // pitch in halfs (272 B rows)
#define SA_HI_ 0
#define SA_LO_ (SA_HI_ + 128 * ALD_ * 2)          // 34816
#define SW_HI_ (SA_LO_ + 128 * ALD_ * 2)          // 69632
#define SW_LO_ (SW_HI_ + 128 * WLDH_ * 2)         // 104448
#define PSM_BYTES_ (SW_LO_ + 128 * WLDH_ * 2)     // 139264

__device__ __forceinline__ uint32_t smem_u32(const void* p) {
    uint32_t a;
    asm("{ .reg .u64 t; cvta.to.shared.u64 t, %1; cvt.u32.u64 %0, t; }"
        : "=r"(a) : "l"(p));
    return a;
}
__device__ __forceinline__ void ldsm_x4_trans(uint32_t* r, uint32_t addr) {
    asm volatile("ldmatrix.sync.aligned.m8n8.x4.trans.shared.b16 {%0,%1,%2,%3}, [%4];"
                 : "=r"(r[0]), "=r"(r[1]), "=r"(r[2]), "=r"(r[3]) : "r"(addr));
}
__device__ __forceinline__ void ldsm_x2(uint32_t& b0, uint32_t& b1, uint32_t addr) {
    asm volatile("ldmatrix.sync.aligned.m8n8.x2.shared.b16 {%0,%1}, [%2];"
                 : "=r"(b0), "=r"(b1) : "r"(addr));
}
__device__ __forceinline__ void mma16816(float* d, const uint32_t* a,
                                         uint32_t b0, uint32_t b1) {
    asm volatile(
        "mma.sync.aligned.m16n8k16.row.col.f32.bf16.bf16.f32 "
        "{%0,%1,%2,%3}, {%4,%5,%6,%7}, {%8,%9}, {%0,%1,%2,%3};"
        : "+f"(d[0]), "+f"(d[1]), "+f"(d[2]), "+f"(d[3])
        : "r"(a[0]), "r"(a[1]), "r"(a[2]), "r"(a[3]), "r"(b0), "r"(b1));
}
// split a float4 into hi/lo bf16 pairs
__device__ __forceinline__ void split4(float4 v, uint2& hi, uint2& lo) {
    float vv[4] = {v.x, v.y, v.z, v.w};
    unsigned short h[4], l[4];
#pragma unroll
    for (int e = 0; e < 4; e++) {
        __nv_bfloat16 hb = __float2bfloat16(vv[e]);
        __nv_bfloat16 lb = __float2bfloat16(vv[e] - __bfloat162float(hb));
        h[e] = __bfloat16_as_ushort(hb);
        l[e] = __bfloat16_as_ushort(lb);
    }
    hi = make_uint2((uint32_t)h[0] | ((uint32_t)h[1] << 16),
                    (uint32_t)h[2] | ((uint32_t)h[3] << 16));
    lo = make_uint2((uint32_t)l[0] | ((uint32_t)l[1] << 16),
                    (uint32_t)l[2] | ((uint32_t)l[3] << 16));
}

__global__ void __launch_bounds__(256, 1) proj_mma_kernel(
    const float* __restrict__ x, const float* __restrict__ wq,
    const float* __restrict__ wk, const float* __restrict__ wv)
{
    extern __shared__ char sm[];
    const uint32_t smb = smem_u32(sm);
    const int t = threadIdx.x;
    const int pxbase = blockIdx.x * 128;
    const int b = blockIdx.y;
    const int mat = blockIdx.z;
    const float* wsrc = (mat == 0) ? wq : (mat == 1) ? wk : wv;

    // ---- X tile: load [128ch][128px], split bf16, store [ch][px] (8B STS) ----
#pragma unroll
    for (int j = 0; j < 16; j++) {
        int idx = t + j * 256;            // 4096 float4 loads
        int c  = idx >> 5;                // 32 float4 per channel row
        int p4 = idx & 31;
        float4 v = *(const float4*)(x + ((size_t)(b * C_ + c)) * HW_ + pxbase + p4 * 4);
        uint2 hi, lo; split4(v, hi, lo);
        uint32_t off = (uint32_t)(c * ALD_ + p4 * 4) * 2;
        *(uint2*)(sm + SA_HI_ + off) = hi;
        *(uint2*)(sm + SA_LO_ + off) = lo;
    }
    // ---- W: convert raw fp32 -> split bf16 padded [n][136] in SMEM ----
#pragma unroll
    for (int j = 0; j < 16; j++) {
        int idx = t + j * 256;            // 4096 float4 = 128 n x 32 k-quads
        int n  = idx >> 5;
        int k4 = idx & 31;
        float4 v = *(const float4*)(wsrc + n * 128 + k4 * 4);
        uint2 hi, lo; split4(v, hi, lo);
        uint32_t off = (uint32_t)(n * WLDH_ + k4 * 4) * 2;
        *(uint2*)(sm + SW_HI_ + off) = hi;
        *(uint2*)(sm + SW_LO_ + off) = lo;
    }
    __syncthreads();

    // ---- warp tiles: warp w -> px strip (w&3)*32, out half (w>>2)*64 ----
    const int w = t >> 5, lane = t & 31;
    const int m0 = (w & 3) * 32;
    const int n0 = (w >> 2) * 64;
    const int lq = lane & 15;

    // A (trans) lane address base: row k = (lane&7) + ((lane>>4)&1)*8, col m
    const uint32_t a_base = smb + SA_HI_ +
        (uint32_t)(((lane & 7) + ((lane >> 4) & 1) * 8) * ALD_ +
                   (m0 + ((lane >> 3) & 1) * 8)) * 2;
    // B lane address base: row n = n0 + (lq&7), k byte offset ((lq>>3)&1)*16
    const uint32_t b_base = smb + SW_HI_ +
        (uint32_t)((n0 + (lq & 7)) * WLDH_) * 2 + ((lq >> 3) & 1) * 16;

    float acc[2][8][4];
#pragma unroll
    for (int mt = 0; mt < 2; mt++)
#pragma unroll
        for (int nt = 0; nt < 8; nt++)
#pragma unroll
            for (int e = 0; e < 4; e++) acc[mt][nt][e] = 0.f;

#pragma unroll
    for (int ks = 0; ks < 8; ks++) {
        uint32_t ahi[2][4], alo[2][4];
#pragma unroll
        for (int mt = 0; mt < 2; mt++) {
            uint32_t aa = a_base + (uint32_t)(ks * 16 * ALD_ * 2 + mt * 32);
            ldsm_x4_trans(ahi[mt], aa);
            ldsm_x4_trans(alo[mt], aa + (SA_LO_ - SA_HI_));
        }
#pragma unroll
        for (int nt = 0; nt < 8; nt++) {
            uint32_t ba = b_base + (uint32_t)(nt * 8 * WLDH_ * 2 + ks * 32);
            uint32_t bh0, bh1, bl0, bl1;
            ldsm_x2(bh0, bh1, ba);
            ldsm_x2(bl0, bl1, ba + (SW_LO_ - SW_HI_));
#pragma unroll
            for (int mt = 0; mt < 2; mt++) {
                mma16816(acc[mt][nt], ahi[mt], bh0, bh1);
                mma16816(acc[mt][nt], ahi[mt], bl0, bl1);
                mma16816(acc[mt][nt], alo[mt], bh0, bh1);
            }
        }
    }

    // ---- epilogue: write chunked g_qkv layout ----
#pragma unroll
    for (int mt = 0; mt < 2; mt++) {
#pragma unroll
        for (int nt = 0; nt < 8; nt++) {
            int nn = n0 + nt * 8 + (lane & 3) * 2;   // out channel (even)
            int cc = nn >> 4, ch16 = nn & 15;
            int flat = pxbase + m0 + mt * 16 + (lane >> 2);
            float* dst = g_qkv + (size_t)mat * MAT_STRIDE_ +
                         (size_t)(b * NC_ + cc) * CHUNK_STRIDE_ +
                         (size_t)flat * 16 + ch16;
            *(float2*)dst          = make_float2(acc[mt][nt][0], acc[mt][nt][1]);
            *(float2*)(dst + 128)  = make_float2(acc[mt][nt][2], acc[mt][nt][3]);  // px+8
        }
    }
}

// ---------------- Kernel 2: windowed attention (R5 design: 16x8, 512 thr) ----
#define TW_ 16
#define TH_ 8
#define KW_ (TW_ + KS_ - 1)        // 22
#define KH_ (TH_ + KS_ - 1)        // 14
#define NGR_ 4
#define PLANE_ (KH_ * KW_)          // 308
#define TILE_F4_ (4 * PLANE_)       // 1232
#define RED_STRIDE_ 65
#define SMEM_TILES_F4_ (NGR_ * 2 * TILE_F4_)
#define SMEM_BYTES_ (SMEM_TILES_F4_ * 16 + 128 * RED_STRIDE_ * 4 + 112 * 4)

__device__ __forceinline__ void cp_stage(float4* __restrict__ dst,
                                         const float* __restrict__ base,
                                         int y0, int x0, int pid)
{
#pragma unroll
    for (int it = 0; it < 10; it++) {
        int i = pid + it * 128;
        if (i < TILE_F4_) {
            int c4  = i / PLANE_;
            int rem = i - c4 * PLANE_;
            int yy  = rem / KW_;
            int xx  = rem - yy * KW_;
            int gy = y0 - PAD_ + yy, gx = x0 - PAD_ + xx;
            bool inb = ((unsigned)gy < H_) && ((unsigned)gx < W_);
            const float* src = base + ((size_t)(inb ? gy : 0) * W_ + (inb ? gx : 0)) * CC_ + c4 * 4;
            unsigned daddr = (unsigned)__cvta_generic_to_shared(dst + i);
            int sz = inb ? 16 : 0;
            asm volatile("cp.async.cg.shared.global [%0], [%1], 16, %2;"
                         :: "r"(daddr), "l"(src), "r"(sz));
        }
    }
}
__device__ __forceinline__ void cp_commit() {
    asm volatile("cp.async.commit_group;" ::: "memory");
}
__device__ __forceinline__ void cp_wait_all() {
    asm volatile("cp.async.wait_all;" ::: "memory");
}
__device__ __forceinline__ void group_bar(int g) {
    asm volatile("bar.sync %0, %1;" :: "r"(1 + g), "r"(128) : "memory");
}

__global__ void __launch_bounds__(512, 1) attn_kernel(
    const float* __restrict__ relx, const float* __restrict__ rely,
    float* __restrict__ out)
{
    extern __shared__ float4 sm4[];
    float* red  = (float*)(sm4 + SMEM_TILES_F4_);
    float* srel = red + 128 * RED_STRIDE_;

    const int t   = threadIdx.x;
    const int g   = t >> 7;
    const int pid = t & 127;
    const int tx  = pid & 15, ty = pid >> 4;
    const int b   = blockIdx.z;
    const int x0  = blockIdx.x * TW_, y0 = blockIdx.y * TH_;
    const int px  = x0 + tx, py = y0 + ty;

    if (t < 112) srel[t] = (t < 56) ? relx[t] : rely[t - 56];

    float4* tile = sm4 + g * (2 * TILE_F4_);
    const float* kb = g_qkv + MAT_STRIDE_;
    const float* vb = g_qkv + 2 * MAT_STRIDE_;

    cp_stage(tile,            kb + (size_t)(b * NC_ + 2 * g    ) * CHUNK_STRIDE_, y0, x0, pid);
    cp_stage(tile + TILE_F4_, kb + (size_t)(b * NC_ + 2 * g + 1) * CHUNK_STRIDE_, y0, x0, pid);
    cp_commit();
    cp_wait_all();
    group_bar(g);

    float logit[49];
#pragma unroll
    for (int i = 0; i < 49; i++) logit[i] = 0.f;
    float qxs[8], qys[8];
#pragma unroll
    for (int i = 0; i < 8; i++) { qxs[i] = 0.f; qys[i] = 0.f; }

#pragma unroll 1
    for (int s = 0; s < 2; s++) {
        const float4* tp = tile + s * TILE_F4_;
        const float4* qp = (const float4*)(g_qkv +
            (size_t)(b * NC_ + 2 * g + s) * CHUNK_STRIDE_ +
            ((size_t)py * W_ + px) * CC_);
        float4 q0 = qp[0], q1 = qp[1], q2 = qp[2], q3 = qp[3];

        qxs[0] += q0.x; qxs[1] += q0.y; qxs[2] += q0.z; qxs[3] += q0.w;
        qxs[4] += q1.x; qxs[5] += q1.y; qxs[6] += q1.z; qxs[7] += q1.w;
        qys[0] += q2.x; qys[1] += q2.y; qys[2] += q2.z; qys[3] += q2.w;
        qys[4] += q3.x; qys[5] += q3.y; qys[6] += q3.z; qys[7] += q3.w;

#pragma unroll
        for (int ki = 0; ki < KS_; ki++) {
#pragma unroll
            for (int kj = 0; kj < KS_; kj++) {
                int o = (ty + ki) * KW_ + tx + kj;
                float4 k0 = tp[0 * PLANE_ + o];
                float4 k1 = tp[1 * PLANE_ + o];
                float4 k2 = tp[2 * PLANE_ + o];
                float4 k3 = tp[3 * PLANE_ + o];
                float sacc = logit[ki * KS_ + kj];
                sacc = fmaf(q0.x, k0.x, sacc); sacc = fmaf(q0.y, k0.y, sacc);
                sacc = fmaf(q0.z, k0.z, sacc); sacc = fmaf(q0.w, k0.w, sacc);
                sacc = fmaf(q1.x, k1.x, sacc); sacc = fmaf(q1.y, k1.y, sacc);
                sacc = fmaf(q1.z, k1.z, sacc); sacc = fmaf(q1.w, k1.w, sacc);
                sacc = fmaf(q2.x, k2.x, sacc); sacc = fmaf(q2.y, k2.y, sacc);
                sacc = fmaf(q2.z, k2.z, sacc); sacc = fmaf(q2.w, k2.w, sacc);
                sacc = fmaf(q3.x, k3.x, sacc); sacc = fmaf(q3.y, k3.y, sacc);
                sacc = fmaf(q3.w, k3.w, sacc); sacc = fmaf(q3.z, k3.z, sacc);
                logit[ki * KS_ + kj] = sacc;
            }
        }
    }

    group_bar(g);
    cp_stage(tile,            vb + (size_t)(b * NC_ + 2 * g    ) * CHUNK_STRIDE_, y0, x0, pid);
    cp_stage(tile + TILE_F4_, vb + (size_t)(b * NC_ + 2 * g + 1) * CHUNK_STRIDE_, y0, x0, pid);
    cp_commit();

    float* rp = red + pid * RED_STRIDE_;
    __syncthreads();
    if (g == 0) {
#pragma unroll
        for (int j = 0; j < 49; j++) rp[j] = logit[j];
#pragma unroll
        for (int j = 0; j < 8; j++) { rp[49 + j] = qxs[j]; rp[57 + j] = qys[j]; }
    }
    __syncthreads();
    if (g == 1) {
#pragma unroll
        for (int j = 0; j < 49; j++) rp[j] += logit[j];
#pragma unroll
        for (int j = 0; j < 8; j++) { rp[49 + j] += qxs[j]; rp[57 + j] += qys[j]; }
    }
    __syncthreads();
    if (g == 2) {
#pragma unroll
        for (int j = 0; j < 49; j++) rp[j] += logit[j];
#pragma unroll
        for (int j = 0; j < 8; j++) { rp[49 + j] += qxs[j]; rp[57 + j] += qys[j]; }
    }
    __syncthreads();
    if (g == 3) {
#pragma unroll
        for (int j = 0; j < 49; j++) rp[j] += logit[j];
#pragma unroll
        for (int j = 0; j < 8; j++) { rp[49 + j] += qxs[j]; rp[57 + j] += qys[j]; }
    }
    __syncthreads();
#pragma unroll
    for (int j = 0; j < 49; j++) logit[j] = rp[j];
#pragma unroll
    for (int j = 0; j < 8; j++) { qxs[j] = rp[49 + j]; qys[j] = rp[57 + j]; }

    float bxv[7], byv[7];
#pragma unroll
    for (int kj = 0; kj < 7; kj++) {
        float s = 0.f;
#pragma unroll
        for (int xi = 0; xi < 8; xi++) s = fmaf(qxs[xi], srel[xi * 7 + kj], s);
        bxv[kj] = s;
    }
#pragma unroll
    for (int ki = 0; ki < 7; ki++) {
        float s = 0.f;
#pragma unroll
        for (int yi = 0; yi < 8; yi++) s = fmaf(qys[yi], srel[56 + yi * 7 + ki], s);
        byv[ki] = s;
    }
    float m = -1e30f;
#pragma unroll
    for (int ki = 0; ki < 7; ki++)
#pragma unroll
        for (int kj = 0; kj < 7; kj++) {
            float l = logit[ki * 7 + kj] + bxv[kj] + byv[ki];
            logit[ki * 7 + kj] = l;
            m = fmaxf(m, l);
        }
    float ssum = 0.f;
#pragma unroll
    for (int i = 0; i < 49; i++) {
        float e = __expf(logit[i] - m);
        logit[i] = e;
        ssum += e;
    }
    float inv = 1.f / ssum;
#pragma unroll
    for (int i = 0; i < 49; i++) logit[i] *= inv;

    cp_wait_all();
    group_bar(g);

#pragma unroll 1
    for (int s = 0; s < 2; s++) {
        const float4* tp = tile + s * TILE_F4_;
        float4 o0 = make_float4(0.f, 0.f, 0.f, 0.f), o1 = o0, o2 = o0, o3 = o0;
#pragma unroll
        for (int ki = 0; ki < KS_; ki++) {
#pragma unroll
            for (int kj = 0; kj < KS_; kj++) {
                float a = logit[ki * KS_ + kj];
                int o = (ty + ki) * KW_ + tx + kj;
                float4 v0 = tp[0 * PLANE_ + o];
                float4 v1 = tp[1 * PLANE_ + o];
                float4 v2 = tp[2 * PLANE_ + o];
                float4 v3 = tp[3 * PLANE_ + o];
                o0.x = fmaf(a, v0.x, o0.x); o0.y = fmaf(a, v0.y, o0.y);
                o0.z = fmaf(a, v0.z, o0.z); o0.w = fmaf(a, v0.w, o0.w);
                o1.x = fmaf(a, v1.x, o1.x); o1.y = fmaf(a, v1.y, o1.y);
                o1.z = fmaf(a, v1.z, o1.z); o1.w = fmaf(a, v1.w, o1.w);
                o2.x = fmaf(a, v2.x, o2.x); o2.y = fmaf(a, v2.y, o2.y);
                o2.z = fmaf(a, v2.z, o2.z); o2.w = fmaf(a, v2.w, o2.w);
                o3.x = fmaf(a, v3.x, o3.x); o3.y = fmaf(a, v3.y, o3.y);
                o3.z = fmaf(a, v3.z, o3.z); o3.w = fmaf(a, v3.w, o3.w);
            }
        }
        int c = 2 * g + s;
        size_t ob = ((size_t)(b * C_ + c * CC_) * H_ + py) * W_ + px;
        out[ob +  0 * HW_] = o0.x; out[ob +  1 * HW_] = o0.y;
        out[ob +  2 * HW_] = o0.z; out[ob +  3 * HW_] = o0.w;
        out[ob +  4 * HW_] = o1.x; out[ob +  5 * HW_] = o1.y;
        out[ob +  6 * HW_] = o1.z; out[ob +  7 * HW_] = o1.w;
        out[ob +  8 * HW_] = o2.x; out[ob +  9 * HW_] = o2.y;
        out[ob + 10 * HW_] = o2.z; out[ob + 11 * HW_] = o2.w;
        out[ob + 12 * HW_] = o3.x; out[ob + 13 * HW_] = o3.y;
        out[ob + 14 * HW_] = o3.z; out[ob + 15 * HW_] = o3.w;
    }
}

// ---------------- launch -----------------------------------------------------
extern "C" void kernel_launch(void* const* d_in, const int* in_sizes, int n_in,
                              void* d_out, int out_size)
{
    const float* x    = (const float*)d_in[0];
    const float* wq   = (const float*)d_in[1];
    const float* wk   = (const float*)d_in[2];
    const float* wv   = (const float*)d_in[3];
    const float* relx = (const float*)d_in[4];
    const float* rely = (const float*)d_in[5];
    float* out = (float*)d_out;

    cudaFuncSetAttribute(proj_mma_kernel,
                         cudaFuncAttributeMaxDynamicSharedMemorySize, PSM_BYTES_);
    cudaFuncSetAttribute(attn_kernel,
                         cudaFuncAttributeMaxDynamicSharedMemorySize, SMEM_BYTES_);

    proj_mma_kernel<<<dim3(32, B_, 3), 256, PSM_BYTES_>>>(x, wq, wk, wv);
    attn_kernel<<<dim3(W_ / TW_, H_ / TH_, B_), 512, SMEM_BYTES_>>>(relx, rely, out);
}

// round 11
// speedup vs baseline: 1.4944x; 1.0300x over previous
#include <cuda_runtime.h>
#include <cuda_bf16.h>
#include <cstdint>

#define B_   4
#define C_   128
#define H_   64
#define W_   64
#define KS_  7
#define PAD_ 3
#define NC_  8      // channel chunks
#define CC_  16     // channels per chunk ( == O/GROUPS )
#define HW_  (H_*W_)

#define CHUNK_STRIDE_ ((size_t)H_*W_*CC_)            // per (b,cc) plane
#define MAT_STRIDE_   ((size_t)B_*NC_*H_*W_*CC_)     // per q/k/v matrix

// Scratch for q,k,v in chunked pixel-major layout: [mat][b][cc][y][x][16]
__device__ __align__(16) float g_qkv[3ull * B_ * NC_ * H_ * W_ * CC_];

// ---------------- Kernel 1: QKV projection via mma.sync bf16-split -----------
// grid = (32 px-tiles, 4 batches); 256 threads. One CTA does all 3 mats:
// X loaded+converted once, W buffers reused per mat.
#define WLDH_ 136
#define ALD_ 136                       // pitch in halfs (272 B rows)
#define SA_HI_ 0
#define SA_LO_ (SA_HI_ + 128 * ALD_ * 2)          // 34816
#define SW_HI_ (SA_LO_ + 128 * ALD_ * 2)          // 69632
#define SW_LO_ (SW_HI_ + 128 * WLDH_ * 2)         // 104448
#define PSM_BYTES_ (SW_LO_ + 128 * WLDH_ * 2)     // 139264

__device__ __forceinline__ uint32_t smem_u32(const void* p) {
    uint32_t a;
    asm("{ .reg .u64 t; cvta.to.shared.u64 t, %1; cvt.u32.u64 %0, t; }"
        : "=r"(a) : "l"(p));
    return a;
}
__device__ __forceinline__ void ldsm_x4_trans(uint32_t* r, uint32_t addr) {
    asm volatile("ldmatrix.sync.aligned.m8n8.x4.trans.shared.b16 {%0,%1,%2,%3}, [%4];"
                 : "=r"(r[0]), "=r"(r[1]), "=r"(r[2]), "=r"(r[3]) : "r"(addr));
}
__device__ __forceinline__ void ldsm_x2(uint32_t& b0, uint32_t& b1, uint32_t addr) {
    asm volatile("ldmatrix.sync.aligned.m8n8.x2.shared.b16 {%0,%1}, [%2];"
                 : "=r"(b0), "=r"(b1) : "r"(addr));
}
__device__ __forceinline__ void mma16816(float* d, const uint32_t* a,
                                         uint32_t b0, uint32_t b1) {
    asm volatile(
        "mma.sync.aligned.m16n8k16.row.col.f32.bf16.bf16.f32 "
        "{%0,%1,%2,%3}, {%4,%5,%6,%7}, {%8,%9}, {%0,%1,%2,%3};"
        : "+f"(d[0]), "+f"(d[1]), "+f"(d[2]), "+f"(d[3])
        : "r"(a[0]), "r"(a[1]), "r"(a[2]), "r"(a[3]), "r"(b0), "r"(b1));
}
// split a float4 into hi/lo bf16 pairs
__device__ __forceinline__ void split4(float4 v, uint2& hi, uint2& lo) {
    float vv[4] = {v.x, v.y, v.z, v.w};
    unsigned short h[4], l[4];
#pragma unroll
    for (int e = 0; e < 4; e++) {
        __nv_bfloat16 hb = __float2bfloat16(vv[e]);
        __nv_bfloat16 lb = __float2bfloat16(vv[e] - __bfloat162float(hb));
        h[e] = __bfloat16_as_ushort(hb);
        l[e] = __bfloat16_as_ushort(lb);
    }
    hi = make_uint2((uint32_t)h[0] | ((uint32_t)h[1] << 16),
                    (uint32_t)h[2] | ((uint32_t)h[3] << 16));
    lo = make_uint2((uint32_t)l[0] | ((uint32_t)l[1] << 16),
                    (uint32_t)l[2] | ((uint32_t)l[3] << 16));
}

__global__ void __launch_bounds__(256, 1) proj_mma_kernel(
    const float* __restrict__ x, const float* __restrict__ wq,
    const float* __restrict__ wk, const float* __restrict__ wv)
{
    extern __shared__ char sm[];
    const uint32_t smb = smem_u32(sm);
    const int t = threadIdx.x;
    const int pxbase = blockIdx.x * 128;
    const int b = blockIdx.y;

    // ---- X tile: load [128ch][128px] ONCE, split bf16, store [ch][px] ----
#pragma unroll
    for (int j = 0; j < 16; j++) {
        int idx = t + j * 256;            // 4096 float4 loads
        int c  = idx >> 5;                // 32 float4 per channel row
        int p4 = idx & 31;
        float4 v = *(const float4*)(x + ((size_t)(b * C_ + c)) * HW_ + pxbase + p4 * 4);
        uint2 hi, lo; split4(v, hi, lo);
        uint32_t off = (uint32_t)(c * ALD_ + p4 * 4) * 2;
        *(uint2*)(sm + SA_HI_ + off) = hi;
        *(uint2*)(sm + SA_LO_ + off) = lo;
    }

    const int w = t >> 5, lane = t & 31;
    const int m0 = (w & 3) * 32;
    const int n0 = (w >> 2) * 64;
    const int lq = lane & 15;

    // A (trans) lane address base: row k = (lane&7) + ((lane>>4)&1)*8, col m
    const uint32_t a_base = smb + SA_HI_ +
        (uint32_t)(((lane & 7) + ((lane >> 4) & 1) * 8) * ALD_ +
                   (m0 + ((lane >> 3) & 1) * 8)) * 2;
    // B lane address base: row n = n0 + (lq&7), k byte offset ((lq>>3)&1)*16
    const uint32_t b_base = smb + SW_HI_ +
        (uint32_t)((n0 + (lq & 7)) * WLDH_) * 2 + ((lq >> 3) & 1) * 16;

#pragma unroll 1
    for (int mat = 0; mat < 3; mat++) {
        const float* wsrc = (mat == 0) ? wq : (mat == 1) ? wk : wv;

        // ---- W: convert raw fp32 -> split bf16 padded [n][136] in SMEM ----
#pragma unroll
        for (int j = 0; j < 16; j++) {
            int idx = t + j * 256;        // 4096 float4 = 128 n x 32 k-quads
            int n  = idx >> 5;
            int k4 = idx & 31;
            float4 v = *(const float4*)(wsrc + n * 128 + k4 * 4);
            uint2 hi, lo; split4(v, hi, lo);
            uint32_t off = (uint32_t)(n * WLDH_ + k4 * 4) * 2;
            *(uint2*)(sm + SW_HI_ + off) = hi;
            *(uint2*)(sm + SW_LO_ + off) = lo;
        }
        __syncthreads();

        float acc[2][8][4];
#pragma unroll
        for (int mt = 0; mt < 2; mt++)
#pragma unroll
            for (int nt = 0; nt < 8; nt++)
#pragma unroll
                for (int e = 0; e < 4; e++) acc[mt][nt][e] = 0.f;

#pragma unroll
        for (int ks = 0; ks < 8; ks++) {
            uint32_t ahi[2][4], alo[2][4];
#pragma unroll
            for (int mt = 0; mt < 2; mt++) {
                uint32_t aa = a_base + (uint32_t)(ks * 16 * ALD_ * 2 + mt * 32);
                ldsm_x4_trans(ahi[mt], aa);
                ldsm_x4_trans(alo[mt], aa + (SA_LO_ - SA_HI_));
            }
#pragma unroll
            for (int nt = 0; nt < 8; nt++) {
                uint32_t ba = b_base + (uint32_t)(nt * 8 * WLDH_ * 2 + ks * 32);
                uint32_t bh0, bh1, bl0, bl1;
                ldsm_x2(bh0, bh1, ba);
                ldsm_x2(bl0, bl1, ba + (SW_LO_ - SW_HI_));
#pragma unroll
                for (int mt = 0; mt < 2; mt++) {
                    mma16816(acc[mt][nt], ahi[mt], bh0, bh1);
                    mma16816(acc[mt][nt], ahi[mt], bl0, bl1);
                    mma16816(acc[mt][nt], alo[mt], bh0, bh1);
                }
            }
        }

        // ---- epilogue: write chunked g_qkv layout for this mat ----
#pragma unroll
        for (int mt = 0; mt < 2; mt++) {
#pragma unroll
            for (int nt = 0; nt < 8; nt++) {
                int nn = n0 + nt * 8 + (lane & 3) * 2;   // out channel (even)
                int cc = nn >> 4, ch16 = nn & 15;
                int flat = pxbase + m0 + mt * 16 + (lane >> 2);
                float* dst = g_qkv + (size_t)mat * MAT_STRIDE_ +
                             (size_t)(b * NC_ + cc) * CHUNK_STRIDE_ +
                             (size_t)flat * 16 + ch16;
                *(float2*)dst          = make_float2(acc[mt][nt][0], acc[mt][nt][1]);
                *(float2*)(dst + 128)  = make_float2(acc[mt][nt][2], acc[mt][nt][3]);
            }
        }
        __syncthreads();   // W buffer reusable for next mat
    }
}

// ---------------- Kernel 2: windowed attention (proven R5 design) ------------
#define TW_ 16
#define TH_ 8
#define KW_ (TW_ + KS_ - 1)        // 22
#define KH_ (TH_ + KS_ - 1)        // 14
#define NGR_ 4
#define PLANE_ (KH_ * KW_)          // 308
#define TILE_F4_ (4 * PLANE_)       // 1232
#define RED_STRIDE_ 65
#define SMEM_TILES_F4_ (NGR_ * 2 * TILE_F4_)
#define SMEM_BYTES_ (SMEM_TILES_F4_ * 16 + 128 * RED_STRIDE_ * 4 + 112 * 4)

__device__ __forceinline__ void cp_stage(float4* __restrict__ dst,
                                         const float* __restrict__ base,
                                         int y0, int x0, int pid)
{
#pragma unroll
    for (int it = 0; it < 10; it++) {
        int i = pid + it * 128;
        if (i < TILE_F4_) {
            int c4  = i / PLANE_;
            int rem = i - c4 * PLANE_;
            int yy  = rem / KW_;
            int xx  = rem - yy * KW_;
            int gy = y0 - PAD_ + yy, gx = x0 - PAD_ + xx;
            bool inb = ((unsigned)gy < H_) && ((unsigned)gx < W_);
            const float* src = base + ((size_t)(inb ? gy : 0) * W_ + (inb ? gx : 0)) * CC_ + c4 * 4;
            unsigned daddr = (unsigned)__cvta_generic_to_shared(dst + i);
            int sz = inb ? 16 : 0;
            asm volatile("cp.async.cg.shared.global [%0], [%1], 16, %2;"
                         :: "r"(daddr), "l"(src), "r"(sz));
        }
    }
}
__device__ __forceinline__ void cp_commit() {
    asm volatile("cp.async.commit_group;" ::: "memory");
}
__device__ __forceinline__ void cp_wait_all() {
    asm volatile("cp.async.wait_all;" ::: "memory");
}
__device__ __forceinline__ void group_bar(int g) {
    asm volatile("bar.sync %0, %1;" :: "r"(1 + g), "r"(128) : "memory");
}

__global__ void __launch_bounds__(512, 1) attn_kernel(
    const float* __restrict__ relx, const float* __restrict__ rely,
    float* __restrict__ out)
{
    extern __shared__ float4 sm4[];
    float* red  = (float*)(sm4 + SMEM_TILES_F4_);
    float* srel = red + 128 * RED_STRIDE_;

    const int t   = threadIdx.x;
    const int g   = t >> 7;
    const int pid = t & 127;
    const int tx  = pid & 15, ty = pid >> 4;
    const int b   = blockIdx.z;
    const int x0  = blockIdx.x * TW_, y0 = blockIdx.y * TH_;
    const int px  = x0 + tx, py = y0 + ty;

    if (t < 112) srel[t] = (t < 56) ? relx[t] : rely[t - 56];

    float4* tile = sm4 + g * (2 * TILE_F4_);
    const float* kb = g_qkv + MAT_STRIDE_;
    const float* vb = g_qkv + 2 * MAT_STRIDE_;

    cp_stage(tile,            kb + (size_t)(b * NC_ + 2 * g    ) * CHUNK_STRIDE_, y0, x0, pid);
    cp_stage(tile + TILE_F4_, kb + (size_t)(b * NC_ + 2 * g + 1) * CHUNK_STRIDE_, y0, x0, pid);
    cp_commit();
    cp_wait_all();
    group_bar(g);

    float logit[49];
#pragma unroll
    for (int i = 0; i < 49; i++) logit[i] = 0.f;
    float qxs[8], qys[8];
#pragma unroll
    for (int i = 0; i < 8; i++) { qxs[i] = 0.f; qys[i] = 0.f; }

#pragma unroll 1
    for (int s = 0; s < 2; s++) {
        const float4* tp = tile + s * TILE_F4_;
        const float4* qp = (const float4*)(g_qkv +
            (size_t)(b * NC_ + 2 * g + s) * CHUNK_STRIDE_ +
            ((size_t)py * W_ + px) * CC_);
        float4 q0 = qp[0], q1 = qp[1], q2 = qp[2], q3 = qp[3];

        qxs[0] += q0.x; qxs[1] += q0.y; qxs[2] += q0.z; qxs[3] += q0.w;
        qxs[4] += q1.x; qxs[5] += q1.y; qxs[6] += q1.z; qxs[7] += q1.w;
        qys[0] += q2.x; qys[1] += q2.y; qys[2] += q2.z; qys[3] += q2.w;
        qys[4] += q3.x; qys[5] += q3.y; qys[6] += q3.z; qys[7] += q3.w;

#pragma unroll
        for (int ki = 0; ki < KS_; ki++) {
#pragma unroll
            for (int kj = 0; kj < KS_; kj++) {
                int o = (ty + ki) * KW_ + tx + kj;
                float4 k0 = tp[0 * PLANE_ + o];
                float4 k1 = tp[1 * PLANE_ + o];
                float4 k2 = tp[2 * PLANE_ + o];
                float4 k3 = tp[3 * PLANE_ + o];
                float sacc = logit[ki * KS_ + kj];
                sacc = fmaf(q0.x, k0.x, sacc); sacc = fmaf(q0.y, k0.y, sacc);
                sacc = fmaf(q0.z, k0.z, sacc); sacc = fmaf(q0.w, k0.w, sacc);
                sacc = fmaf(q1.x, k1.x, sacc); sacc = fmaf(q1.y, k1.y, sacc);
                sacc = fmaf(q1.z, k1.z, sacc); sacc = fmaf(q1.w, k1.w, sacc);
                sacc = fmaf(q2.x, k2.x, sacc); sacc = fmaf(q2.y, k2.y, sacc);
                sacc = fmaf(q2.z, k2.z, sacc); sacc = fmaf(q2.w, k2.w, sacc);
                sacc = fmaf(q3.x, k3.x, sacc); sacc = fmaf(q3.y, k3.y, sacc);
                sacc = fmaf(q3.z, k3.z, sacc); sacc = fmaf(q3.w, k3.w, sacc);
                logit[ki * KS_ + kj] = sacc;
            }
        }
    }

    group_bar(g);
    cp_stage(tile,            vb + (size_t)(b * NC_ + 2 * g    ) * CHUNK_STRIDE_, y0, x0, pid);
    cp_stage(tile + TILE_F4_, vb + (size_t)(b * NC_ + 2 * g + 1) * CHUNK_STRIDE_, y0, x0, pid);
    cp_commit();

    float* rp = red + pid * RED_STRIDE_;
    __syncthreads();
    if (g == 0) {
#pragma unroll
        for (int j = 0; j < 49; j++) rp[j] = logit[j];
#pragma unroll
        for (int j = 0; j < 8; j++) { rp[49 + j] = qxs[j]; rp[57 + j] = qys[j]; }
    }
    __syncthreads();
    if (g == 1) {
#pragma unroll
        for (int j = 0; j < 49; j++) rp[j] += logit[j];
#pragma unroll
        for (int j = 0; j < 8; j++) { rp[49 + j] += qxs[j]; rp[57 + j] += qys[j]; }
    }
    __syncthreads();
    if (g == 2) {
#pragma unroll
        for (int j = 0; j < 49; j++) rp[j] += logit[j];
#pragma unroll
        for (int j = 0; j < 8; j++) { rp[49 + j] += qxs[j]; rp[57 + j] += qys[j]; }
    }
    __syncthreads();
    if (g == 3) {
#pragma unroll
        for (int j = 0; j < 49; j++) rp[j] += logit[j];
#pragma unroll
        for (int j = 0; j < 8; j++) { rp[49 + j] += qxs[j]; rp[57 + j] += qys[j]; }
    }
    __syncthreads();
#pragma unroll
    for (int j = 0; j < 49; j++) logit[j] = rp[j];
#pragma unroll
    for (int j = 0; j < 8; j++) { qxs[j] = rp[49 + j]; qys[j] = rp[57 + j]; }

    float bxv[7], byv[7];
#pragma unroll
    for (int kj = 0; kj < 7; kj++) {
        float s = 0.f;
#pragma unroll
        for (int xi = 0; xi < 8; xi++) s = fmaf(qxs[xi], srel[xi * 7 + kj], s);
        bxv[kj] = s;
    }
#pragma unroll
    for (int ki = 0; ki < 7; ki++) {
        float s = 0.f;
#pragma unroll
        for (int yi = 0; yi < 8; yi++) s = fmaf(qys[yi], srel[56 + yi * 7 + ki], s);
        byv[ki] = s;
    }
    float m = -1e30f;
#pragma unroll
    for (int ki = 0; ki < 7; ki++)
#pragma unroll
        for (int kj = 0; kj < 7; kj++) {
            float l = logit[ki * 7 + kj] + bxv[kj] + byv[ki];
            logit[ki * 7 + kj] = l;
            m = fmaxf(m, l);
        }
    float ssum = 0.f;
#pragma unroll
    for (int i = 0; i < 49; i++) {
        float e = __expf(logit[i] - m);
        logit[i] = e;
        ssum += e;
    }
    float inv = 1.f / ssum;
#pragma unroll
    for (int i = 0; i < 49; i++) logit[i] *= inv;

    cp_wait_all();
    group_bar(g);

#pragma unroll 1
    for (int s = 0; s < 2; s++) {
        const float4* tp = tile + s * TILE_F4_;
        float4 o0 = make_float4(0.f, 0.f, 0.f, 0.f), o1 = o0, o2 = o0, o3 = o0;
#pragma unroll
        for (int ki = 0; ki < KS_; ki++) {
#pragma unroll
            for (int kj = 0; kj < KS_; kj++) {
                float a = logit[ki * KS_ + kj];
                int o = (ty + ki) * KW_ + tx + kj;
                float4 v0 = tp[0 * PLANE_ + o];
                float4 v1 = tp[1 * PLANE_ + o];
                float4 v2 = tp[2 * PLANE_ + o];
                float4 v3 = tp[3 * PLANE_ + o];
                o0.x = fmaf(a, v0.x, o0.x); o0.y = fmaf(a, v0.y, o0.y);
                o0.z = fmaf(a, v0.z, o0.z); o0.w = fmaf(a, v0.w, o0.w);
                o1.x = fmaf(a, v1.x, o1.x); o1.y = fmaf(a, v1.y, o1.y);
                o1.z = fmaf(a, v1.z, o1.z); o1.w = fmaf(a, v1.w, o1.w);
                o2.x = fmaf(a, v2.x, o2.x); o2.y = fmaf(a, v2.y, o2.y);
                o2.z = fmaf(a, v2.z, o2.z); o2.w = fmaf(a, v2.w, o2.w);
                o3.x = fmaf(a, v3.x, o3.x); o3.y = fmaf(a, v3.y, o3.y);
                o3.z = fmaf(a, v3.z, o3.z); o3.w = fmaf(a, v3.w, o3.w);
            }
        }
        int c = 2 * g + s;
        size_t ob = ((size_t)(b * C_ + c * CC_) * H_ + py) * W_ + px;
        out[ob +  0 * HW_] = o0.x; out[ob +  1 * HW_] = o0.y;
        out[ob +  2 * HW_] = o0.z; out[ob +  3 * HW_] = o0.w;
        out[ob +  4 * HW_] = o1.x; out[ob +  5 * HW_] = o1.y;
        out[ob +  6 * HW_] = o1.z; out[ob +  7 * HW_] = o1.w;
        out[ob +  8 * HW_] = o2.x; out[ob +  9 * HW_] = o2.y;
        out[ob + 10 * HW_] = o2.z; out[ob + 11 * HW_] = o2.w;
        out[ob + 12 * HW_] = o3.x; out[ob + 13 * HW_] = o3.y;
        out[ob + 14 * HW_] = o3.z; out[ob + 15 * HW_] = o3.w;
    }
}

// ---------------- launch -----------------------------------------------------
extern "C" void kernel_launch(void* const* d_in, const int* in_sizes, int n_in,
                              void* d_out, int out_size)
{
    const float* x    = (const float*)d_in[0];
    const float* wq   = (const float*)d_in[1];
    const float* wk   = (const float*)d_in[2];
    const float* wv   = (const float*)d_in[3];
    const float* relx = (const float*)d_in[4];
    const float* rely = (const float*)d_in[5];
    float* out = (float*)d_out;

    cudaFuncSetAttribute(proj_mma_kernel,
                         cudaFuncAttributeMaxDynamicSharedMemorySize, PSM_BYTES_);
    cudaFuncSetAttribute(attn_kernel,
                         cudaFuncAttributeMaxDynamicSharedMemorySize, SMEM_BYTES_);

    proj_mma_kernel<<<dim3(32, B_), 256, PSM_BYTES_>>>(x, wq, wk, wv);
    attn_kernel<<<dim3(W_ / TW_, H_ / TH_, B_), 512, SMEM_BYTES_>>>(relx, rely, out);
}

// round 12
// speedup vs baseline: 1.5007x; 1.0042x over previous
#include <cuda_runtime.h>
#include <cuda_bf16.h>
#include <cstdint>

#define B_   4
#define C_   128
#define H_   64
#define W_   64
#define KS_  7
#define PAD_ 3
#define NC_  8      // channel chunks
#define CC_  16     // channels per chunk ( == O/GROUPS )
#define HW_  (H_*W_)

#define CHUNK_STRIDE_ ((size_t)H_*W_*CC_)            // per (b,cc) plane
#define MAT_STRIDE_   ((size_t)B_*NC_*H_*W_*CC_)     // per q/k/v matrix

// Scratch for q,k,v in chunked pixel-major layout: [mat][b][cc][y][x][16]
__device__ __align__(16) float g_qkv[3ull * B_ * NC_ * H_ * W_ * CC_];

// ---------------- Kernel 1: QKV projection via mma.sync bf16-split -----------
// grid = (64 px-tiles of 64px, 4 batches); 256 threads; 2 CTAs/SM.
// SMEM: A hi/lo [ch=128][px=72 pitch] halfs; W hi/lo [n=128][k=136 pitch].
#define WLDH_ 136
#define PALD_ 72                               // A pitch in halfs (144 B rows)
#define PSA_HI_ 0
#define PSA_LO_ (PSA_HI_ + 128 * PALD_ * 2)    // 18432
#define PSW_HI_ (PSA_LO_ + 128 * PALD_ * 2)    // 36864
#define PSW_LO_ (PSW_HI_ + 128 * WLDH_ * 2)    // 71680
#define PSM_BYTES_ (PSW_LO_ + 128 * WLDH_ * 2) // 106496  -> 2 CTAs/SM

__device__ __forceinline__ uint32_t smem_u32(const void* p) {
    uint32_t a;
    asm("{ .reg .u64 t; cvta.to.shared.u64 t, %1; cvt.u32.u64 %0, t; }"
        : "=r"(a) : "l"(p));
    return a;
}
__device__ __forceinline__ void ldsm_x4_trans(uint32_t* r, uint32_t addr) {
    asm volatile("ldmatrix.sync.aligned.m8n8.x4.trans.shared.b16 {%0,%1,%2,%3}, [%4];"
                 : "=r"(r[0]), "=r"(r[1]), "=r"(r[2]), "=r"(r[3]) : "r"(addr));
}
__device__ __forceinline__ void ldsm_x2(uint32_t& b0, uint32_t& b1, uint32_t addr) {
    asm volatile("ldmatrix.sync.aligned.m8n8.x2.shared.b16 {%0,%1}, [%2];"
                 : "=r"(b0), "=r"(b1) : "r"(addr));
}
__device__ __forceinline__ void mma16816(float* d, const uint32_t* a,
                                         uint32_t b0, uint32_t b1) {
    asm volatile(
        "mma.sync.aligned.m16n8k16.row.col.f32.bf16.bf16.f32 "
        "{%0,%1,%2,%3}, {%4,%5,%6,%7}, {%8,%9}, {%0,%1,%2,%3};"
        : "+f"(d[0]), "+f"(d[1]), "+f"(d[2]), "+f"(d[3])
        : "r"(a[0]), "r"(a[1]), "r"(a[2]), "r"(a[3]), "r"(b0), "r"(b1));
}
// split a float4 into hi/lo bf16 pairs
__device__ __forceinline__ void split4(float4 v, uint2& hi, uint2& lo) {
    float vv[4] = {v.x, v.y, v.z, v.w};
    unsigned short h[4], l[4];
#pragma unroll
    for (int e = 0; e < 4; e++) {
        __nv_bfloat16 hb = __float2bfloat16(vv[e]);
        __nv_bfloat16 lb = __float2bfloat16(vv[e] - __bfloat162float(hb));
        h[e] = __bfloat16_as_ushort(hb);
        l[e] = __bfloat16_as_ushort(lb);
    }
    hi = make_uint2((uint32_t)h[0] | ((uint32_t)h[1] << 16),
                    (uint32_t)h[2] | ((uint32_t)h[3] << 16));
    lo = make_uint2((uint32_t)l[0] | ((uint32_t)l[1] << 16),
                    (uint32_t)l[2] | ((uint32_t)l[3] << 16));
}

__global__ void __launch_bounds__(256, 2) proj_mma_kernel(
    const float* __restrict__ x, const float* __restrict__ wq,
    const float* __restrict__ wk, const float* __restrict__ wv)
{
    extern __shared__ char sm[];
    const uint32_t smb = smem_u32(sm);
    const int t = threadIdx.x;
    const int pxbase = blockIdx.x * 64;
    const int b = blockIdx.y;

    // ---- X tile: load [128ch][64px] ONCE, split bf16, store [ch][px] ----
#pragma unroll
    for (int j = 0; j < 8; j++) {
        int idx = t + j * 256;            // 2048 float4 loads
        int c  = idx >> 4;                // 16 float4 per channel row
        int p4 = idx & 15;
        float4 v = *(const float4*)(x + ((size_t)(b * C_ + c)) * HW_ + pxbase + p4 * 4);
        uint2 hi, lo; split4(v, hi, lo);
        uint32_t off = (uint32_t)(c * PALD_ + p4 * 4) * 2;
        *(uint2*)(sm + PSA_HI_ + off) = hi;
        *(uint2*)(sm + PSA_LO_ + off) = lo;
    }

    const int w = t >> 5, lane = t & 31;
    const int m0 = (w & 1) * 32;          // px strip within 64
    const int n0 = (w >> 1) * 32;         // out-channel strip (4 strips of 32)
    const int lq = lane & 15;

    // A (trans) lane address base: row k = (lane&7) + ((lane>>4)&1)*8, col m
    const uint32_t a_base = smb + PSA_HI_ +
        (uint32_t)(((lane & 7) + ((lane >> 4) & 1) * 8) * PALD_ +
                   (m0 + ((lane >> 3) & 1) * 8)) * 2;
    // B lane address base: row n = n0 + (lq&7), k byte offset ((lq>>3)&1)*16
    const uint32_t b_base = smb + PSW_HI_ +
        (uint32_t)((n0 + (lq & 7)) * WLDH_) * 2 + ((lq >> 3) & 1) * 16;

#pragma unroll 1
    for (int mat = 0; mat < 3; mat++) {
        const float* wsrc = (mat == 0) ? wq : (mat == 1) ? wk : wv;

        // ---- W: convert raw fp32 -> split bf16 padded [n][136] in SMEM ----
#pragma unroll
        for (int j = 0; j < 16; j++) {
            int idx = t + j * 256;        // 4096 float4 = 128 n x 32 k-quads
            int n  = idx >> 5;
            int k4 = idx & 31;
            float4 v = *(const float4*)(wsrc + n * 128 + k4 * 4);
            uint2 hi, lo; split4(v, hi, lo);
            uint32_t off = (uint32_t)(n * WLDH_ + k4 * 4) * 2;
            *(uint2*)(sm + PSW_HI_ + off) = hi;
            *(uint2*)(sm + PSW_LO_ + off) = lo;
        }
        __syncthreads();

        float acc[2][4][4];
#pragma unroll
        for (int mt = 0; mt < 2; mt++)
#pragma unroll
            for (int nt = 0; nt < 4; nt++)
#pragma unroll
                for (int e = 0; e < 4; e++) acc[mt][nt][e] = 0.f;

#pragma unroll
        for (int ks = 0; ks < 8; ks++) {
            uint32_t ahi[2][4], alo[2][4];
#pragma unroll
            for (int mt = 0; mt < 2; mt++) {
                uint32_t aa = a_base + (uint32_t)(ks * 16 * PALD_ * 2 + mt * 32);
                ldsm_x4_trans(ahi[mt], aa);
                ldsm_x4_trans(alo[mt], aa + (PSA_LO_ - PSA_HI_));
            }
#pragma unroll
            for (int nt = 0; nt < 4; nt++) {
                uint32_t ba = b_base + (uint32_t)(nt * 8 * WLDH_ * 2 + ks * 32);
                uint32_t bh0, bh1, bl0, bl1;
                ldsm_x2(bh0, bh1, ba);
                ldsm_x2(bl0, bl1, ba + (PSW_LO_ - PSW_HI_));
#pragma unroll
                for (int mt = 0; mt < 2; mt++) {
                    mma16816(acc[mt][nt], ahi[mt], bh0, bh1);
                    mma16816(acc[mt][nt], ahi[mt], bl0, bl1);
                    mma16816(acc[mt][nt], alo[mt], bh0, bh1);
                }
            }
        }

        // ---- epilogue: write chunked g_qkv layout for this mat ----
#pragma unroll
        for (int mt = 0; mt < 2; mt++) {
#pragma unroll
            for (int nt = 0; nt < 4; nt++) {
                int nn = n0 + nt * 8 + (lane & 3) * 2;   // out channel (even)
                int cc = nn >> 4, ch16 = nn & 15;
                int flat = pxbase + m0 + mt * 16 + (lane >> 2);
                float* dst = g_qkv + (size_t)mat * MAT_STRIDE_ +
                             (size_t)(b * NC_ + cc) * CHUNK_STRIDE_ +
                             (size_t)flat * 16 + ch16;
                *(float2*)dst          = make_float2(acc[mt][nt][0], acc[mt][nt][1]);
                *(float2*)(dst + 128)  = make_float2(acc[mt][nt][2], acc[mt][nt][3]);
            }
        }
        __syncthreads();   // W buffer reusable for next mat
    }
}

// ---------------- Kernel 2: windowed attention (proven R5 design) ------------
#define TW_ 16
#define TH_ 8
#define KW_ (TW_ + KS_ - 1)        // 22
#define KH_ (TH_ + KS_ - 1)        // 14
#define NGR_ 4
#define PLANE_ (KH_ * KW_)          // 308
#define TILE_F4_ (4 * PLANE_)       // 1232
#define RED_STRIDE_ 65
#define SMEM_TILES_F4_ (NGR_ * 2 * TILE_F4_)
#define SMEM_BYTES_ (SMEM_TILES_F4_ * 16 + 128 * RED_STRIDE_ * 4 + 112 * 4)

__device__ __forceinline__ void cp_stage(float4* __restrict__ dst,
                                         const float* __restrict__ base,
                                         int y0, int x0, int pid)
{
#pragma unroll
    for (int it = 0; it < 10; it++) {
        int i = pid + it * 128;
        if (i < TILE_F4_) {
            int c4  = i / PLANE_;
            int rem = i - c4 * PLANE_;
            int yy  = rem / KW_;
            int xx  = rem - yy * KW_;
            int gy = y0 - PAD_ + yy, gx = x0 - PAD_ + xx;
            bool inb = ((unsigned)gy < H_) && ((unsigned)gx < W_);
            const float* src = base + ((size_t)(inb ? gy : 0) * W_ + (inb ? gx : 0)) * CC_ + c4 * 4;
            unsigned daddr = (unsigned)__cvta_generic_to_shared(dst + i);
            int sz = inb ? 16 : 0;
            asm volatile("cp.async.cg.shared.global [%0], [%1], 16, %2;"
                         :: "r"(daddr), "l"(src), "r"(sz));
        }
    }
}
__device__ __forceinline__ void cp_commit() {
    asm volatile("cp.async.commit_group;" ::: "memory");
}
__device__ __forceinline__ void cp_wait_all() {
    asm volatile("cp.async.wait_all;" ::: "memory");
}
__device__ __forceinline__ void group_bar(int g) {
    asm volatile("bar.sync %0, %1;" :: "r"(1 + g), "r"(128) : "memory");
}

__global__ void __launch_bounds__(512, 1) attn_kernel(
    const float* __restrict__ relx, const float* __restrict__ rely,
    float* __restrict__ out)
{
    extern __shared__ float4 sm4[];
    float* red  = (float*)(sm4 + SMEM_TILES_F4_);
    float* srel = red + 128 * RED_STRIDE_;

    const int t   = threadIdx.x;
    const int g   = t >> 7;
    const int pid = t & 127;
    const int tx  = pid & 15, ty = pid >> 4;
    const int b   = blockIdx.z;
    const int x0  = blockIdx.x * TW_, y0 = blockIdx.y * TH_;
    const int px  = x0 + tx, py = y0 + ty;

    if (t < 112) srel[t] = (t < 56) ? relx[t] : rely[t - 56];

    float4* tile = sm4 + g * (2 * TILE_F4_);
    const float* kb = g_qkv + MAT_STRIDE_;
    const float* vb = g_qkv + 2 * MAT_STRIDE_;

    cp_stage(tile,            kb + (size_t)(b * NC_ + 2 * g    ) * CHUNK_STRIDE_, y0, x0, pid);
    cp_stage(tile + TILE_F4_, kb + (size_t)(b * NC_ + 2 * g + 1) * CHUNK_STRIDE_, y0, x0, pid);
    cp_commit();
    cp_wait_all();
    group_bar(g);

    float logit[49];
#pragma unroll
    for (int i = 0; i < 49; i++) logit[i] = 0.f;
    float qxs[8], qys[8];
#pragma unroll
    for (int i = 0; i < 8; i++) { qxs[i] = 0.f; qys[i] = 0.f; }

#pragma unroll 1
    for (int s = 0; s < 2; s++) {
        const float4* tp = tile + s * TILE_F4_;
        const float4* qp = (const float4*)(g_qkv +
            (size_t)(b * NC_ + 2 * g + s) * CHUNK_STRIDE_ +
            ((size_t)py * W_ + px) * CC_);
        float4 q0 = qp[0], q1 = qp[1], q2 = qp[2], q3 = qp[3];

        qxs[0] += q0.x; qxs[1] += q0.y; qxs[2] += q0.z; qxs[3] += q0.w;
        qxs[4] += q1.x; qxs[5] += q1.y; qxs[6] += q1.z; qxs[7] += q1.w;
        qys[0] += q2.x; qys[1] += q2.y; qys[2] += q2.z; qys[3] += q2.w;
        qys[4] += q3.x; qys[5] += q3.y; qys[6] += q3.z; qys[7] += q3.w;

#pragma unroll
        for (int ki = 0; ki < KS_; ki++) {
#pragma unroll
            for (int kj = 0; kj < KS_; kj++) {
                int o = (ty + ki) * KW_ + tx + kj;
                float4 k0 = tp[0 * PLANE_ + o];
                float4 k1 = tp[1 * PLANE_ + o];
                float4 k2 = tp[2 * PLANE_ + o];
                float4 k3 = tp[3 * PLANE_ + o];
                float sacc = logit[ki * KS_ + kj];
                sacc = fmaf(q0.x, k0.x, sacc); sacc = fmaf(q0.y, k0.y, sacc);
                sacc = fmaf(q0.z, k0.z, sacc); sacc = fmaf(q0.w, k0.w, sacc);
                sacc = fmaf(q1.x, k1.x, sacc); sacc = fmaf(q1.y, k1.y, sacc);
                sacc = fmaf(q1.z, k1.z, sacc); sacc = fmaf(q1.w, k1.w, sacc);
                sacc = fmaf(q2.x, k2.x, sacc); sacc = fmaf(q2.y, k2.y, sacc);
                sacc = fmaf(q2.z, k2.z, sacc); sacc = fmaf(q2.w, k2.w, sacc);
                sacc = fmaf(q3.x, k3.x, sacc); sacc = fmaf(q3.y, k3.y, sacc);
                sacc = fmaf(q3.z, k3.z, sacc); sacc = fmaf(q3.w, k3.w, sacc);
                logit[ki * KS_ + kj] = sacc;
            }
        }
    }

    group_bar(g);
    cp_stage(tile,            vb + (size_t)(b * NC_ + 2 * g    ) * CHUNK_STRIDE_, y0, x0, pid);
    cp_stage(tile + TILE_F4_, vb + (size_t)(b * NC_ + 2 * g + 1) * CHUNK_STRIDE_, y0, x0, pid);
    cp_commit();

    float* rp = red + pid * RED_STRIDE_;
    __syncthreads();
    if (g == 0) {
#pragma unroll
        for (int j = 0; j < 49; j++) rp[j] = logit[j];
#pragma unroll
        for (int j = 0; j < 8; j++) { rp[49 + j] = qxs[j]; rp[57 + j] = qys[j]; }
    }
    __syncthreads();
    if (g == 1) {
#pragma unroll
        for (int j = 0; j < 49; j++) rp[j] += logit[j];
#pragma unroll
        for (int j = 0; j < 8; j++) { rp[49 + j] += qxs[j]; rp[57 + j] += qys[j]; }
    }
    __syncthreads();
    if (g == 2) {
#pragma unroll
        for (int j = 0; j < 49; j++) rp[j] += logit[j];
#pragma unroll
        for (int j = 0; j < 8; j++) { rp[49 + j] += qxs[j]; rp[57 + j] += qys[j]; }
    }
    __syncthreads();
    if (g == 3) {
#pragma unroll
        for (int j = 0; j < 49; j++) rp[j] += logit[j];
#pragma unroll
        for (int j = 0; j < 8; j++) { rp[49 + j] += qxs[j]; rp[57 + j] += qys[j]; }
    }
    __syncthreads();
#pragma unroll
    for (int j = 0; j < 49; j++) logit[j] = rp[j];
#pragma unroll
    for (int j = 0; j < 8; j++) { qxs[j] = rp[49 + j]; qys[j] = rp[57 + j]; }

    float bxv[7], byv[7];
#pragma unroll
    for (int kj = 0; kj < 7; kj++) {
        float s = 0.f;
#pragma unroll
        for (int xi = 0; xi < 8; xi++) s = fmaf(qxs[xi], srel[xi * 7 + kj], s);
        bxv[kj] = s;
    }
#pragma unroll
    for (int ki = 0; ki < 7; ki++) {
        float s = 0.f;
#pragma unroll
        for (int yi = 0; yi < 8; yi++) s = fmaf(qys[yi], srel[56 + yi * 7 + ki], s);
        byv[ki] = s;
    }
    float m = -1e30f;
#pragma unroll
    for (int ki = 0; ki < 7; ki++)
#pragma unroll
        for (int kj = 0; kj < 7; kj++) {
            float l = logit[ki * 7 + kj] + bxv[kj] + byv[ki];
            logit[ki * 7 + kj] = l;
            m = fmaxf(m, l);
        }
    float ssum = 0.f;
#pragma unroll
    for (int i = 0; i < 49; i++) {
        float e = __expf(logit[i] - m);
        logit[i] = e;
        ssum += e;
    }
    float inv = 1.f / ssum;
#pragma unroll
    for (int i = 0; i < 49; i++) logit[i] *= inv;

    cp_wait_all();
    group_bar(g);

#pragma unroll 1
    for (int s = 0; s < 2; s++) {
        const float4* tp = tile + s * TILE_F4_;
        float4 o0 = make_float4(0.f, 0.f, 0.f, 0.f), o1 = o0, o2 = o0, o3 = o0;
#pragma unroll
        for (int ki = 0; ki < KS_; ki++) {
#pragma unroll
            for (int kj = 0; kj < KS_; kj++) {
                float a = logit[ki * KS_ + kj];
                int o = (ty + ki) * KW_ + tx + kj;
                float4 v0 = tp[0 * PLANE_ + o];
                float4 v1 = tp[1 * PLANE_ + o];
                float4 v2 = tp[2 * PLANE_ + o];
                float4 v3 = tp[3 * PLANE_ + o];
                o0.x = fmaf(a, v0.x, o0.x); o0.y = fmaf(a, v0.y, o0.y);
                o0.z = fmaf(a, v0.z, o0.z); o0.w = fmaf(a, v0.w, o0.w);
                o1.x = fmaf(a, v1.x, o1.x); o1.y = fmaf(a, v1.y, o1.y);
                o1.z = fmaf(a, v1.z, o1.z); o1.w = fmaf(a, v1.w, o1.w);
                o2.x = fmaf(a, v2.x, o2.x); o2.y = fmaf(a, v2.y, o2.y);
                o2.z = fmaf(a, v2.z, o2.z); o2.w = fmaf(a, v2.w, o2.w);
                o3.x = fmaf(a, v3.x, o3.x); o3.y = fmaf(a, v3.y, o3.y);
                o3.z = fmaf(a, v3.z, o3.z); o3.w = fmaf(a, v3.w, o3.w);
            }
        }
        int c = 2 * g + s;
        size_t ob = ((size_t)(b * C_ + c * CC_) * H_ + py) * W_ + px;
        out[ob +  0 * HW_] = o0.x; out[ob +  1 * HW_] = o0.y;
        out[ob +  2 * HW_] = o0.z; out[ob +  3 * HW_] = o0.w;
        out[ob +  4 * HW_] = o1.x; out[ob +  5 * HW_] = o1.y;
        out[ob +  6 * HW_] = o1.z; out[ob +  7 * HW_] = o1.w;
        out[ob +  8 * HW_] = o2.x; out[ob +  9 * HW_] = o2.y;
        out[ob + 10 * HW_] = o2.z; out[ob + 11 * HW_] = o2.w;
        out[ob + 12 * HW_] = o3.x; out[ob + 13 * HW_] = o3.y;
        out[ob + 14 * HW_] = o3.z; out[ob + 15 * HW_] = o3.w;
    }
}

// ---------------- launch -----------------------------------------------------
extern "C" void kernel_launch(void* const* d_in, const int* in_sizes, int n_in,
                              void* d_out, int out_size)
{
    const float* x    = (const float*)d_in[0];
    const float* wq   = (const float*)d_in[1];
    const float* wk   = (const float*)d_in[2];
    const float* wv   = (const float*)d_in[3];
    const float* relx = (const float*)d_in[4];
    const float* rely = (const float*)d_in[5];
    float* out = (float*)d_out;

    cudaFuncSetAttribute(proj_mma_kernel,
                         cudaFuncAttributeMaxDynamicSharedMemorySize, PSM_BYTES_);
    cudaFuncSetAttribute(attn_kernel,
                         cudaFuncAttributeMaxDynamicSharedMemorySize, SMEM_BYTES_);

    proj_mma_kernel<<<dim3(64, B_), 256, PSM_BYTES_>>>(x, wq, wk, wv);
    attn_kernel<<<dim3(W_ / TW_, H_ / TH_, B_), 512, SMEM_BYTES_>>>(relx, rely, out);
}